// round 3
// baseline (speedup 1.0000x reference)
#include <cuda_runtime.h>
#include <math.h>

#define NN 100000
#define EMAX 1600000
#define FIN 128
#define FHID 32
#define FOUT 16
#define EPSV 1e-5f
#define NSLOPE 0.2f

// ---------------- scratch (device globals; allocation-free) ----------------
__device__ float g_bufA[NN * 64];
__device__ float g_bufB[NN * 64];
__device__ float g_dinv[NN];
__device__ int   g_deg[NN];
__device__ int   g_rowptr[NN + 1];
__device__ int   g_cursor[NN];
__device__ int   g_csr[EMAX];
__device__ float g_als[NN * 2];
__device__ float g_ald[NN * 2];

// ---------------- helpers ----------------
__device__ __forceinline__ float lrelu(float x) { return x > 0.f ? x : NSLOPE * x; }
__device__ __forceinline__ float wsum32(float v) {
#pragma unroll
    for (int o = 16; o; o >>= 1) v += __shfl_xor_sync(0xffffffffu, v, o);
    return v;
}

// ---------------- CSR build ----------------
__global__ void k_zero_deg(int n) {
    int i = blockIdx.x * blockDim.x + threadIdx.x;
    if (i < n) g_deg[i] = 0;
}
__global__ void k_hist(const int* __restrict__ dst, int e) {
    int i = blockIdx.x * blockDim.x + threadIdx.x;
    if (i < e) atomicAdd(&g_deg[dst[i]], 1);
}
__global__ void k_scan(int n) {
    __shared__ int ssum[1024];
    int t = threadIdx.x;
    int chunk = (n + 1023) / 1024;
    int lo = t * chunk, hi = min(lo + chunk, n);
    int s = 0;
    for (int i = lo; i < hi; ++i) s += g_deg[i];
    ssum[t] = s;
    __syncthreads();
#pragma unroll
    for (int off = 1; off < 1024; off <<= 1) {
        int v = (t >= off) ? ssum[t - off] : 0;
        __syncthreads();
        ssum[t] += v;
        __syncthreads();
    }
    int run = t ? ssum[t - 1] : 0;
    for (int i = lo; i < hi; ++i) {
        int d = g_deg[i];
        g_rowptr[i] = run;
        g_cursor[i] = run;
        g_dinv[i] = rsqrtf((float)(d + 1));
        run += d;
    }
    if (t == 1023) g_rowptr[n] = ssum[1023];
}
__global__ void k_scatter(const int* __restrict__ src, const int* __restrict__ dst, int e) {
    int i = blockIdx.x * blockDim.x + threadIdx.x;
    if (i >= e) return;
    int pos = atomicAdd(&g_cursor[dst[i]], 1);
    g_csr[pos] = src[i];
}

// ---------------- tiled GEMM: Y[n,F] = X[n,K] @ W[K,F] ----------------
// ALMODE 0: plain. ALMODE 1: also compute attention logits per head
// (H=2, HF=F/2): g_als[row,h] = sum_col_in_head Y[row,col]*a_s[col], same for a_d.
template <int K, int F, int RPB, int ALMODE>
__global__ void k_gemm_t(const float* __restrict__ X, const float* __restrict__ W,
                         float* __restrict__ Y,
                         const float* __restrict__ a_s, const float* __restrict__ a_d,
                         int n) {
    constexpr int RPT = RPB * F / 256;
    __shared__ float Ws[K * F];
    __shared__ float Xs[RPB * K];
    __shared__ float salS[ALMODE ? RPB * 2 : 1];
    __shared__ float salD[ALMODE ? RPB * 2 : 1];
    int tid = threadIdx.x;
    for (int i = tid; i < K * F; i += 256) Ws[i] = W[i];
    int row0 = blockIdx.x * RPB;
    for (int i = tid; i < RPB * K; i += 256) {
        int r = row0 + i / K;
        Xs[i] = (r < n) ? X[(long)r * K + (i % K)] : 0.f;
    }
    if (ALMODE && tid < RPB * 2) { salS[tid] = 0.f; salD[tid] = 0.f; }
    __syncthreads();
    int col = tid % F, rg = tid / F;
    float acc[RPT];
#pragma unroll
    for (int r = 0; r < RPT; ++r) acc[r] = 0.f;
#pragma unroll 8
    for (int k = 0; k < K; ++k) {
        float wv = Ws[k * F + col];
#pragma unroll
        for (int r = 0; r < RPT; ++r)
            acc[r] = fmaf(Xs[(rg * RPT + r) * K + k], wv, acc[r]);
    }
#pragma unroll
    for (int r = 0; r < RPT; ++r) {
        int row = row0 + rg * RPT + r;
        if (row < n) Y[(long)row * F + col] = acc[r];
    }
    if (ALMODE) {
        constexpr int HF = F / 2;
        int head = col / HF;
        float asv = __ldg(&a_s[col]);
        float adv = __ldg(&a_d[col]);
#pragma unroll
        for (int r = 0; r < RPT; ++r) {
            int loc = rg * RPT + r;
            atomicAdd(&salS[loc * 2 + head], acc[r] * asv);
            atomicAdd(&salD[loc * 2 + head], acc[r] * adv);
        }
        __syncthreads();
        if (tid < RPB * 2) {
            int row = row0 + tid / 2;
            if (row < n) {
                g_als[row * 2 + (tid & 1)] = salS[(tid / 2) * 2 + (tid & 1)];
                g_ald[row * 2 + (tid & 1)] = salD[(tid / 2) * 2 + (tid & 1)];
            }
        }
    }
}

// ---------------- GCN gather (warp/node) + bias + BN + ReLU ----------------
__global__ void k_gcn_agg(const float* __restrict__ h, float* __restrict__ out,
                          const float* __restrict__ bias,
                          const float* __restrict__ bg, const float* __restrict__ bb,
                          const float* __restrict__ bm, const float* __restrict__ bv, int n) {
    int w = (blockIdx.x * blockDim.x + threadIdx.x) >> 5;
    int lane = threadIdx.x & 31;
    if (w >= n) return;
    int r0 = g_rowptr[w], r1 = g_rowptr[w + 1];
    float dd = g_dinv[w];
    float acc = h[(long)w * FHID + lane] * dd;   // self contribution (norm = dd*dd)
    for (int base = r0; base < r1; base += 32) {
        int j = base + lane;
        int cnt = min(32, r1 - base);
        int sj = 0; float dv = 0.f;
        if (j < r1) { sj = g_csr[j]; dv = g_dinv[sj]; }
        for (int q = 0; q < cnt; ++q) {
            int s = __shfl_sync(0xffffffffu, sj, q);
            float d = __shfl_sync(0xffffffffu, dv, q);
            acc = fmaf(h[(long)s * FHID + lane], d, acc);
        }
    }
    acc = acc * dd + __ldg(&bias[lane]);
    float sc = __ldg(&bg[lane]) * rsqrtf(__ldg(&bv[lane]) + EPSV);
    float o = (acc - __ldg(&bm[lane])) * sc + __ldg(&bb[lane]);
    out[(long)w * FHID + lane] = fmaxf(o, 0.f);
}

// ---------------- fused GAT (warp/node): single-sweep softmax-free agg ----------------
// alpha = exp(e)/sum(exp(e)) computed without max subtraction (|e| small).
// MODE 0: F=32, epilogue bias+ReLU. MODE 1: F=16, epilogue bias+log_softmax.
template <int F, int MODE>
__global__ void k_gat_agg(const float* __restrict__ hg, float* __restrict__ out,
                          const float* __restrict__ bias, int n) {
    int w = (blockIdx.x * blockDim.x + threadIdx.x) >> 5;
    int lane = threadIdx.x & 31;
    if (w >= n) return;
    int r0 = g_rowptr[w], r1 = g_rowptr[w + 1];
    float ald0 = g_ald[w * 2], ald1 = g_ald[w * 2 + 1];
    float w0 = expf(lrelu(g_als[w * 2] + ald0));
    float w1 = expf(lrelu(g_als[w * 2 + 1] + ald1));
    float s0p = (lane == 0) ? w0 : 0.f;
    float s1p = (lane == 0) ? w1 : 0.f;

    if (MODE == 0) {  // F = 32
        float acc0 = w0 * hg[(long)w * 64 + lane];
        float acc1 = w1 * hg[(long)w * 64 + 32 + lane];
        for (int base = r0; base < r1; base += 32) {
            int j = base + lane;
            int cnt = min(32, r1 - base);
            int sj = 0; float a0 = 0.f, a1 = 0.f;
            if (j < r1) {
                sj = g_csr[j];
                a0 = expf(lrelu(g_als[sj * 2] + ald0));
                a1 = expf(lrelu(g_als[sj * 2 + 1] + ald1));
            }
            s0p += a0; s1p += a1;
            for (int q = 0; q < cnt; ++q) {
                int s = __shfl_sync(0xffffffffu, sj, q);
                float b0 = __shfl_sync(0xffffffffu, a0, q);
                float b1 = __shfl_sync(0xffffffffu, a1, q);
                acc0 = fmaf(b0, hg[(long)s * 64 + lane], acc0);
                acc1 = fmaf(b1, hg[(long)s * 64 + 32 + lane], acc1);
            }
        }
        float s0 = wsum32(s0p), s1 = wsum32(s1p);
        float o = acc0 * (0.5f / s0) + acc1 * (0.5f / s1) + __ldg(&bias[lane]);
        out[(long)w * 32 + lane] = fmaxf(o, 0.f);
    } else {  // F = 16, lane = head*16 + f
        int head = lane >> 4;
        float acc = (head ? w1 : w0) * hg[(long)w * 32 + lane];
        for (int base = r0; base < r1; base += 32) {
            int j = base + lane;
            int cnt = min(32, r1 - base);
            int sj = 0; float a0 = 0.f, a1 = 0.f;
            if (j < r1) {
                sj = g_csr[j];
                a0 = expf(lrelu(g_als[sj * 2] + ald0));
                a1 = expf(lrelu(g_als[sj * 2 + 1] + ald1));
            }
            s0p += a0; s1p += a1;
            for (int q = 0; q < cnt; ++q) {
                int s = __shfl_sync(0xffffffffu, sj, q);
                float b0 = __shfl_sync(0xffffffffu, a0, q);
                float b1 = __shfl_sync(0xffffffffu, a1, q);
                acc = fmaf(head ? b1 : b0, hg[(long)s * 32 + lane], acc);
            }
        }
        float s0 = wsum32(s0p), s1 = wsum32(s1p);
        float v = acc / (head ? s1 : s0);
        v = 0.5f * (v + __shfl_xor_sync(0xffffffffu, v, 16));  // mean over heads
        v += __ldg(&bias[lane & 15]);
        float mx = v;
#pragma unroll
        for (int o = 8; o; o >>= 1) mx = fmaxf(mx, __shfl_xor_sync(0xffffffffu, mx, o));
        float se = expf(v - mx);
#pragma unroll
        for (int o = 8; o; o >>= 1) se += __shfl_xor_sync(0xffffffffu, se, o);
        float ls = logf(se) + mx;
        if (lane < 16) out[(long)w * 16 + lane] = v - ls;
    }
}

// ---------------- host ----------------
static inline int cdiv(long a, int b) { return (int)((a + b - 1) / b); }

extern "C" void kernel_launch(void* const* d_in, const int* in_sizes, int n_in,
                              void* d_out, int out_size) {
    const float* x   = (const float*)d_in[0];
    const int*   ei  = (const int*)d_in[1];
    const float* g1W = (const float*)d_in[2];
    const float* g1b = (const float*)d_in[3];
    const float* b1g = (const float*)d_in[4];
    const float* b1b = (const float*)d_in[5];
    const float* b1m = (const float*)d_in[6];
    const float* b1v = (const float*)d_in[7];
    const float* a1W = (const float*)d_in[8];
    const float* a1s = (const float*)d_in[9];
    const float* a1d = (const float*)d_in[10];
    const float* a1b = (const float*)d_in[11];
    const float* g2W = (const float*)d_in[12];
    const float* g2b = (const float*)d_in[13];
    const float* b2g = (const float*)d_in[14];
    const float* b2b = (const float*)d_in[15];
    const float* b2m = (const float*)d_in[16];
    const float* b2v = (const float*)d_in[17];
    const float* a2W = (const float*)d_in[18];
    const float* a2s = (const float*)d_in[19];
    const float* a2d = (const float*)d_in[20];
    const float* a2b = (const float*)d_in[21];

    int n = in_sizes[0] / FIN;
    int e = in_sizes[1] / 2;
    const int* src = ei;
    const int* dst = ei + e;

    float *pA, *pB;
    cudaGetSymbolAddress((void**)&pA, g_bufA);
    cudaGetSymbolAddress((void**)&pB, g_bufB);

    const int B = 256;
    int nwarp_blocks = cdiv((long)n * 32, B);

    // ---- CSR build ----
    k_zero_deg<<<cdiv(n, B), B>>>(n);
    k_hist<<<cdiv(e, B), B>>>(dst, e);
    k_scan<<<1, 1024>>>(n);
    k_scatter<<<cdiv(e, B), B>>>(src, dst, e);

    // ---- GCN1 ----
    k_gemm_t<FIN, FHID, 32, 0><<<cdiv(n, 32), B>>>(x, g1W, pA, nullptr, nullptr, n);
    k_gcn_agg<<<nwarp_blocks, B>>>(pA, pB, g1b, b1g, b1b, b1m, b1v, n);

    // ---- GAT1 (HID->HID, 2 heads, mean): GEMM computes logits in epilogue ----
    k_gemm_t<FHID, 64, 16, 1><<<cdiv(n, 16), B>>>(pB, a1W, pA, a1s, a1d, n);
    k_gat_agg<32, 0><<<nwarp_blocks, B>>>(pA, pB, a1b, n);

    // ---- GCN2 ----
    k_gemm_t<FHID, FHID, 32, 0><<<cdiv(n, 32), B>>>(pB, g2W, pA, nullptr, nullptr, n);
    k_gcn_agg<<<nwarp_blocks, B>>>(pA, pB, g2b, b2g, b2b, b2m, b2v, n);

    // ---- GAT2 (HID->OUT, 2 heads, mean) + final log_softmax ----
    k_gemm_t<FHID, 2 * FOUT, 32, 1><<<cdiv(n, 32), B>>>(pB, a2W, pA, a2s, a2d, n);
    k_gat_agg<16, 1><<<nwarp_blocks, B>>>(pA, (float*)d_out, a2b, n);
}

// round 4
// speedup vs baseline: 1.2687x; 1.2687x over previous
#include <cuda_runtime.h>
#include <math.h>

#define NN 100000
#define EMAX 1600000
#define FIN 128
#define FHID 32
#define FOUT 16
#define EPSV 1e-5f
#define NSLOPE 0.2f

// ---------------- scratch (device globals; allocation-free) ----------------
__device__ float g_bufA[NN * 64];
__device__ float g_bufB[NN * 64];
__device__ float g_dinv[NN];
__device__ int   g_deg[NN];
__device__ int   g_rowptr[NN + 1];
__device__ int   g_cursor[NN];
__device__ int   g_csr[EMAX];
__device__ float g_als[NN * 2];
__device__ float g_ald[NN * 2];

// ---------------- helpers ----------------
__device__ __forceinline__ float lrelu(float x) { return x > 0.f ? x : NSLOPE * x; }
__device__ __forceinline__ float wsum32(float v) {
#pragma unroll
    for (int o = 16; o; o >>= 1) v += __shfl_xor_sync(0xffffffffu, v, o);
    return v;
}
__device__ __forceinline__ float wsum16(float v) {
#pragma unroll
    for (int o = 8; o; o >>= 1) v += __shfl_xor_sync(0xffffffffu, v, o);
    return v;
}

// ---------------- CSR build ----------------
__global__ void k_zero_deg(int n) {
    int i = blockIdx.x * blockDim.x + threadIdx.x;
    if (i < n) g_deg[i] = 0;
}
__global__ void k_hist(const int* __restrict__ dst, int e) {
    int i = blockIdx.x * blockDim.x + threadIdx.x;
    if (i < e) atomicAdd(&g_deg[dst[i]], 1);
}
__global__ void k_scan(int n) {
    __shared__ int ssum[1024];
    int t = threadIdx.x;
    int chunk = (n + 1023) / 1024;
    int lo = t * chunk, hi = min(lo + chunk, n);
    int s = 0;
    for (int i = lo; i < hi; ++i) s += g_deg[i];
    ssum[t] = s;
    __syncthreads();
#pragma unroll
    for (int off = 1; off < 1024; off <<= 1) {
        int v = (t >= off) ? ssum[t - off] : 0;
        __syncthreads();
        ssum[t] += v;
        __syncthreads();
    }
    int run = t ? ssum[t - 1] : 0;
    for (int i = lo; i < hi; ++i) {
        int d = g_deg[i];
        g_rowptr[i] = run;
        g_cursor[i] = run;
        g_dinv[i] = rsqrtf((float)(d + 1));
        run += d;
    }
    if (t == 1023) g_rowptr[n] = ssum[1023];
}
__global__ void k_scatter(const int* __restrict__ src, const int* __restrict__ dst, int e) {
    int i = blockIdx.x * blockDim.x + threadIdx.x;
    if (i >= e) return;
    int pos = atomicAdd(&g_cursor[dst[i]], 1);
    g_csr[pos] = src[i];
}

// ---------------- tiled GEMM: Y[n,F] = X[n,K] @ W[K,F] ----------------
// ALMODE 0: plain.
// ALMODE 1 (F==64, RPB=16): attention logits via full-warp reduction.
//   Layout: warp w covers cols (w&1)*32..+31 (== head w&1) of row-group rg=tid/64.
// ALMODE 2 (F==32, RPB=32): logits via half-warp reduction (head = lane>>4).
template <int K, int F, int RPB, int ALMODE>
__global__ void k_gemm_t(const float* __restrict__ X, const float* __restrict__ W,
                         float* __restrict__ Y,
                         const float* __restrict__ a_s, const float* __restrict__ a_d,
                         int n) {
    constexpr int RPT = RPB * F / 256;
    __shared__ float Ws[K * F];
    __shared__ float Xs[RPB * K];
    int tid = threadIdx.x;
    for (int i = tid; i < K * F; i += 256) Ws[i] = W[i];
    int row0 = blockIdx.x * RPB;
    for (int i = tid; i < RPB * K; i += 256) {
        int r = row0 + i / K;
        Xs[i] = (r < n) ? X[(long)r * K + (i % K)] : 0.f;
    }
    __syncthreads();
    int col = tid % F, rg = tid / F;
    float acc[RPT];
#pragma unroll
    for (int r = 0; r < RPT; ++r) acc[r] = 0.f;
#pragma unroll 8
    for (int k = 0; k < K; ++k) {
        float wv = Ws[k * F + col];
#pragma unroll
        for (int r = 0; r < RPT; ++r)
            acc[r] = fmaf(Xs[(rg * RPT + r) * K + k], wv, acc[r]);
    }
#pragma unroll
    for (int r = 0; r < RPT; ++r) {
        int row = row0 + rg * RPT + r;
        if (row < n) Y[(long)row * F + col] = acc[r];
    }
    if (ALMODE == 1) {
        // F=64: warp = one head of one row-group; cols of this warp are contiguous.
        int lane = tid & 31;
        int head = (tid >> 5) & 1;
        float asv = __ldg(&a_s[col]);
        float adv = __ldg(&a_d[col]);
#pragma unroll
        for (int r = 0; r < RPT; ++r) {
            float s = wsum32(acc[r] * asv);
            float d = wsum32(acc[r] * adv);
            int row = row0 + rg * RPT + r;
            if (lane == 0 && row < n) {
                g_als[row * 2 + head] = s;
                g_ald[row * 2 + head] = d;
            }
        }
    } else if (ALMODE == 2) {
        // F=32: warp = one row-group; head = lane>>4, 16 cols per head.
        int lane = tid & 31;
        int head = lane >> 4;
        float asv = __ldg(&a_s[col]);
        float adv = __ldg(&a_d[col]);
#pragma unroll
        for (int r = 0; r < RPT; ++r) {
            float s = wsum16(acc[r] * asv);
            float d = wsum16(acc[r] * adv);
            int row = row0 + rg * RPT + r;
            if ((lane & 15) == 0 && row < n) {
                g_als[row * 2 + head] = s;
                g_ald[row * 2 + head] = d;
            }
        }
    }
}

// ---------------- GCN gather (warp/node) + bias + BN + ReLU ----------------
__global__ void k_gcn_agg(const float* __restrict__ h, float* __restrict__ out,
                          const float* __restrict__ bias,
                          const float* __restrict__ bg, const float* __restrict__ bb,
                          const float* __restrict__ bm, const float* __restrict__ bv, int n) {
    int w = (blockIdx.x * blockDim.x + threadIdx.x) >> 5;
    int lane = threadIdx.x & 31;
    if (w >= n) return;
    int r0 = g_rowptr[w], r1 = g_rowptr[w + 1];
    float dd = g_dinv[w];
    float acc = h[(long)w * FHID + lane] * dd;   // self contribution (norm = dd*dd)
    for (int base = r0; base < r1; base += 32) {
        int j = base + lane;
        int cnt = min(32, r1 - base);
        int sj = 0; float dv = 0.f;
        if (j < r1) { sj = g_csr[j]; dv = g_dinv[sj]; }
        for (int q = 0; q < cnt; ++q) {
            int s = __shfl_sync(0xffffffffu, sj, q);
            float d = __shfl_sync(0xffffffffu, dv, q);
            acc = fmaf(h[(long)s * FHID + lane], d, acc);
        }
    }
    acc = acc * dd + __ldg(&bias[lane]);
    float sc = __ldg(&bg[lane]) * rsqrtf(__ldg(&bv[lane]) + EPSV);
    float o = (acc - __ldg(&bm[lane])) * sc + __ldg(&bb[lane]);
    out[(long)w * FHID + lane] = fmaxf(o, 0.f);
}

// ---------------- fused GAT (warp/node): single-sweep softmax-free agg ----------------
// alpha = exp(e)/sum(exp(e)) without max subtraction (|e| small; tol 1e-3).
// MODE 0: F=32, epilogue bias+ReLU. MODE 1: F=16, epilogue bias+log_softmax.
template <int F, int MODE>
__global__ void k_gat_agg(const float* __restrict__ hg, float* __restrict__ out,
                          const float* __restrict__ bias, int n) {
    int w = (blockIdx.x * blockDim.x + threadIdx.x) >> 5;
    int lane = threadIdx.x & 31;
    if (w >= n) return;
    int r0 = g_rowptr[w], r1 = g_rowptr[w + 1];
    float ald0 = g_ald[w * 2], ald1 = g_ald[w * 2 + 1];
    float w0 = expf(lrelu(g_als[w * 2] + ald0));
    float w1 = expf(lrelu(g_als[w * 2 + 1] + ald1));
    float s0p = (lane == 0) ? w0 : 0.f;
    float s1p = (lane == 0) ? w1 : 0.f;

    if (MODE == 0) {  // F = 32
        float acc0 = w0 * hg[(long)w * 64 + lane];
        float acc1 = w1 * hg[(long)w * 64 + 32 + lane];
        for (int base = r0; base < r1; base += 32) {
            int j = base + lane;
            int cnt = min(32, r1 - base);
            int sj = 0; float a0 = 0.f, a1 = 0.f;
            if (j < r1) {
                sj = g_csr[j];
                a0 = expf(lrelu(g_als[sj * 2] + ald0));
                a1 = expf(lrelu(g_als[sj * 2 + 1] + ald1));
            }
            s0p += a0; s1p += a1;
            for (int q = 0; q < cnt; ++q) {
                int s = __shfl_sync(0xffffffffu, sj, q);
                float b0 = __shfl_sync(0xffffffffu, a0, q);
                float b1 = __shfl_sync(0xffffffffu, a1, q);
                acc0 = fmaf(b0, hg[(long)s * 64 + lane], acc0);
                acc1 = fmaf(b1, hg[(long)s * 64 + 32 + lane], acc1);
            }
        }
        float s0 = wsum32(s0p), s1 = wsum32(s1p);
        float o = acc0 * (0.5f / s0) + acc1 * (0.5f / s1) + __ldg(&bias[lane]);
        out[(long)w * 32 + lane] = fmaxf(o, 0.f);
    } else {  // F = 16, lane = head*16 + f
        int head = lane >> 4;
        float acc = (head ? w1 : w0) * hg[(long)w * 32 + lane];
        for (int base = r0; base < r1; base += 32) {
            int j = base + lane;
            int cnt = min(32, r1 - base);
            int sj = 0; float a0 = 0.f, a1 = 0.f;
            if (j < r1) {
                sj = g_csr[j];
                a0 = expf(lrelu(g_als[sj * 2] + ald0));
                a1 = expf(lrelu(g_als[sj * 2 + 1] + ald1));
            }
            s0p += a0; s1p += a1;
            for (int q = 0; q < cnt; ++q) {
                int s = __shfl_sync(0xffffffffu, sj, q);
                float b0 = __shfl_sync(0xffffffffu, a0, q);
                float b1 = __shfl_sync(0xffffffffu, a1, q);
                acc = fmaf(head ? b1 : b0, hg[(long)s * 32 + lane], acc);
            }
        }
        float s0 = wsum32(s0p), s1 = wsum32(s1p);
        float v = acc / (head ? s1 : s0);
        v = 0.5f * (v + __shfl_xor_sync(0xffffffffu, v, 16));  // mean over heads
        v += __ldg(&bias[lane & 15]);
        float mx = v;
#pragma unroll
        for (int o = 8; o; o >>= 1) mx = fmaxf(mx, __shfl_xor_sync(0xffffffffu, mx, o));
        float se = expf(v - mx);
#pragma unroll
        for (int o = 8; o; o >>= 1) se += __shfl_xor_sync(0xffffffffu, se, o);
        float ls = logf(se) + mx;
        if (lane < 16) out[(long)w * 16 + lane] = v - ls;
    }
}

// ---------------- host ----------------
static inline int cdiv(long a, int b) { return (int)((a + b - 1) / b); }

extern "C" void kernel_launch(void* const* d_in, const int* in_sizes, int n_in,
                              void* d_out, int out_size) {
    const float* x   = (const float*)d_in[0];
    const int*   ei  = (const int*)d_in[1];
    const float* g1W = (const float*)d_in[2];
    const float* g1b = (const float*)d_in[3];
    const float* b1g = (const float*)d_in[4];
    const float* b1b = (const float*)d_in[5];
    const float* b1m = (const float*)d_in[6];
    const float* b1v = (const float*)d_in[7];
    const float* a1W = (const float*)d_in[8];
    const float* a1s = (const float*)d_in[9];
    const float* a1d = (const float*)d_in[10];
    const float* a1b = (const float*)d_in[11];
    const float* g2W = (const float*)d_in[12];
    const float* g2b = (const float*)d_in[13];
    const float* b2g = (const float*)d_in[14];
    const float* b2b = (const float*)d_in[15];
    const float* b2m = (const float*)d_in[16];
    const float* b2v = (const float*)d_in[17];
    const float* a2W = (const float*)d_in[18];
    const float* a2s = (const float*)d_in[19];
    const float* a2d = (const float*)d_in[20];
    const float* a2b = (const float*)d_in[21];

    int n = in_sizes[0] / FIN;
    int e = in_sizes[1] / 2;
    const int* src = ei;
    const int* dst = ei + e;

    float *pA, *pB;
    cudaGetSymbolAddress((void**)&pA, g_bufA);
    cudaGetSymbolAddress((void**)&pB, g_bufB);

    const int B = 256;
    int nwarp_blocks = cdiv((long)n * 32, B);

    // ---- CSR build ----
    k_zero_deg<<<cdiv(n, B), B>>>(n);
    k_hist<<<cdiv(e, B), B>>>(dst, e);
    k_scan<<<1, 1024>>>(n);
    k_scatter<<<cdiv(e, B), B>>>(src, dst, e);

    // ---- GCN1 ----
    k_gemm_t<FIN, FHID, 32, 0><<<cdiv(n, 32), B>>>(x, g1W, pA, nullptr, nullptr, n);
    k_gcn_agg<<<nwarp_blocks, B>>>(pA, pB, g1b, b1g, b1b, b1m, b1v, n);

    // ---- GAT1 (HID->HID, 2 heads, mean): GEMM folds logits via warp reduce ----
    k_gemm_t<FHID, 64, 16, 1><<<cdiv(n, 16), B>>>(pB, a1W, pA, a1s, a1d, n);
    k_gat_agg<32, 0><<<nwarp_blocks, B>>>(pA, pB, a1b, n);

    // ---- GCN2 ----
    k_gemm_t<FHID, FHID, 32, 0><<<cdiv(n, 32), B>>>(pB, g2W, pA, nullptr, nullptr, n);
    k_gcn_agg<<<nwarp_blocks, B>>>(pA, pB, g2b, b2g, b2b, b2m, b2v, n);

    // ---- GAT2 (HID->OUT, 2 heads, mean) + final log_softmax ----
    k_gemm_t<FHID, 2 * FOUT, 32, 2><<<cdiv(n, 32), B>>>(pB, a2W, pA, a2s, a2d, n);
    k_gat_agg<16, 1><<<nwarp_blocks, B>>>(pA, (float*)d_out, a2b, n);
}

// round 5
// speedup vs baseline: 1.3626x; 1.0740x over previous
#include <cuda_runtime.h>
#include <math.h>

#define NN 100000
#define EMAX 1600000
#define FIN 128
#define FHID 32
#define FOUT 16
#define EPSV 1e-5f
#define NSLOPE 0.2f

// ---------------- scratch ----------------
__device__ float g_bufA[NN * 64];
__device__ float g_bufB[NN * 64];
__device__ float g_dinv[NN];
__device__ int   g_deg[NN];
__device__ int   g_rowptr[NN + 1];
__device__ int   g_cursor[NN];
__device__ int   g_csr[EMAX];
__device__ float g_al[NN * 4];   // interleaved: [als0, als1, ald0, ald1] per node

// ---------------- helpers ----------------
__device__ __forceinline__ float lrelu(float x) { return x > 0.f ? x : NSLOPE * x; }
__device__ __forceinline__ float wsum32(float v) {
#pragma unroll
    for (int o = 16; o; o >>= 1) v += __shfl_xor_sync(0xffffffffu, v, o);
    return v;
}
__device__ __forceinline__ float wsum16(float v) {
#pragma unroll
    for (int o = 8; o; o >>= 1) v += __shfl_xor_sync(0xffffffffu, v, o);
    return v;
}
__device__ __forceinline__ void f4red(float4& a, int off) {
    a.x += __shfl_xor_sync(0xffffffffu, a.x, off);
    a.y += __shfl_xor_sync(0xffffffffu, a.y, off);
    a.z += __shfl_xor_sync(0xffffffffu, a.z, off);
    a.w += __shfl_xor_sync(0xffffffffu, a.w, off);
}
__device__ __forceinline__ float4 f4shfl(float4 a, int src) {
    float4 r;
    r.x = __shfl_sync(0xffffffffu, a.x, src);
    r.y = __shfl_sync(0xffffffffu, a.y, src);
    r.z = __shfl_sync(0xffffffffu, a.z, src);
    r.w = __shfl_sync(0xffffffffu, a.w, src);
    return r;
}

// ---------------- CSR build ----------------
__global__ void k_zero_deg(int n) {
    int i = blockIdx.x * blockDim.x + threadIdx.x;
    if (i < n) g_deg[i] = 0;
}
__global__ void k_hist(const int* __restrict__ dst, int e) {
    int i = blockIdx.x * blockDim.x + threadIdx.x;
    if (i < e) atomicAdd(&g_deg[dst[i]], 1);
}
__global__ void k_scan(int n) {
    __shared__ int ssum[1024];
    int t = threadIdx.x;
    int chunk = (n + 1023) / 1024;
    int lo = t * chunk, hi = min(lo + chunk, n);
    int s = 0;
    for (int i = lo; i < hi; ++i) s += g_deg[i];
    ssum[t] = s;
    __syncthreads();
#pragma unroll
    for (int off = 1; off < 1024; off <<= 1) {
        int v = (t >= off) ? ssum[t - off] : 0;
        __syncthreads();
        ssum[t] += v;
        __syncthreads();
    }
    int run = t ? ssum[t - 1] : 0;
    for (int i = lo; i < hi; ++i) {
        int d = g_deg[i];
        g_rowptr[i] = run;
        g_cursor[i] = run;
        g_dinv[i] = rsqrtf((float)(d + 1));
        run += d;
    }
    if (t == 1023) g_rowptr[n] = ssum[1023];
}
__global__ void k_scatter(const int* __restrict__ src, const int* __restrict__ dst, int e) {
    int i = blockIdx.x * blockDim.x + threadIdx.x;
    if (i >= e) return;
    int pos = atomicAdd(&g_cursor[dst[i]], 1);
    g_csr[pos] = src[i];
}

// ---------------- tiled GEMM: Y[n,F] = X[n,K] @ W[K,F] ----------------
// ALMODE 0: plain.
// ALMODE 1 (F==64): warp = one head of one row-group; logits via wsum32.
// ALMODE 2 (F==32): warp = one row-group; head = lane>>4; wsum16.
template <int K, int F, int RPB, int ALMODE>
__global__ void k_gemm_t(const float* __restrict__ X, const float* __restrict__ W,
                         float* __restrict__ Y,
                         const float* __restrict__ a_s, const float* __restrict__ a_d,
                         int n) {
    constexpr int RPT = RPB * F / 256;
    __shared__ float Ws[K * F];
    __shared__ float Xs[RPB * K];
    int tid = threadIdx.x;
    for (int i = tid; i < K * F; i += 256) Ws[i] = W[i];
    int row0 = blockIdx.x * RPB;
    for (int i = tid; i < RPB * K; i += 256) {
        int r = row0 + i / K;
        Xs[i] = (r < n) ? X[(long)r * K + (i % K)] : 0.f;
    }
    __syncthreads();
    int col = tid % F, rg = tid / F;
    float acc[RPT];
#pragma unroll
    for (int r = 0; r < RPT; ++r) acc[r] = 0.f;
#pragma unroll 8
    for (int k = 0; k < K; ++k) {
        float wv = Ws[k * F + col];
#pragma unroll
        for (int r = 0; r < RPT; ++r)
            acc[r] = fmaf(Xs[(rg * RPT + r) * K + k], wv, acc[r]);
    }
#pragma unroll
    for (int r = 0; r < RPT; ++r) {
        int row = row0 + rg * RPT + r;
        if (row < n) Y[(long)row * F + col] = acc[r];
    }
    if (ALMODE == 1) {
        int lane = tid & 31;
        int head = (tid >> 5) & 1;
        float asv = __ldg(&a_s[col]);
        float adv = __ldg(&a_d[col]);
#pragma unroll
        for (int r = 0; r < RPT; ++r) {
            float s = wsum32(acc[r] * asv);
            float d = wsum32(acc[r] * adv);
            int row = row0 + rg * RPT + r;
            if (lane == 0 && row < n) {
                g_al[row * 4 + head] = s;
                g_al[row * 4 + 2 + head] = d;
            }
        }
    } else if (ALMODE == 2) {
        int lane = tid & 31;
        int head = lane >> 4;
        float asv = __ldg(&a_s[col]);
        float adv = __ldg(&a_d[col]);
#pragma unroll
        for (int r = 0; r < RPT; ++r) {
            float s = wsum16(acc[r] * asv);
            float d = wsum16(acc[r] * adv);
            int row = row0 + rg * RPT + r;
            if ((lane & 15) == 0 && row < n) {
                g_al[row * 4 + head] = s;
                g_al[row * 4 + 2 + head] = d;
            }
        }
    }
}

// ---------------- GCN gather (warp/node, float4, 4 neighbors/iter) ----------------
__global__ void k_gcn_agg(const float* __restrict__ h, float* __restrict__ out,
                          const float* __restrict__ bias,
                          const float* __restrict__ bg, const float* __restrict__ bb,
                          const float* __restrict__ bm, const float* __restrict__ bv, int n) {
    int w = (blockIdx.x * blockDim.x + threadIdx.x) >> 5;
    int lane = threadIdx.x & 31;
    if (w >= n) return;
    const float4* h4 = (const float4*)h;
    int r0 = g_rowptr[w], r1 = g_rowptr[w + 1];
    float dd = g_dinv[w];
    int g = lane >> 3;      // neighbor slot 0..3
    int c = lane & 7;       // float4 chunk within the 32-float row
    float4 acc = make_float4(0.f, 0.f, 0.f, 0.f);
    if (g == 0) {
        float4 hv = h4[(long)w * 8 + c];
        acc.x = hv.x * dd; acc.y = hv.y * dd; acc.z = hv.z * dd; acc.w = hv.w * dd;
    }
    for (int base = r0; base < r1; base += 32) {
        int j = base + lane;
        int cnt = min(32, r1 - base);
        int sj = 0; float dv = 0.f;
        if (j < r1) { sj = g_csr[j]; dv = g_dinv[sj]; }
        for (int t = 0; t < cnt; t += 4) {
            int q = t + g;
            int s = __shfl_sync(0xffffffffu, sj, q);
            float d = __shfl_sync(0xffffffffu, dv, q);
            if (q < cnt) {
                float4 v = h4[(long)s * 8 + c];
                acc.x = fmaf(v.x, d, acc.x);
                acc.y = fmaf(v.y, d, acc.y);
                acc.z = fmaf(v.z, d, acc.z);
                acc.w = fmaf(v.w, d, acc.w);
            }
        }
    }
    f4red(acc, 8); f4red(acc, 16);
    if (g == 0) {
        const float4* b4 = (const float4*)bias;
        const float4* g4 = (const float4*)bg;
        const float4* bb4 = (const float4*)bb;
        const float4* m4 = (const float4*)bm;
        const float4* v4 = (const float4*)bv;
        float4 bi = __ldg(&b4[c]), gg = __ldg(&g4[c]), bbv = __ldg(&bb4[c]);
        float4 mm = __ldg(&m4[c]), vv = __ldg(&v4[c]);
        float4 o;
        o.x = fmaxf((acc.x * dd + bi.x - mm.x) * (gg.x * rsqrtf(vv.x + EPSV)) + bbv.x, 0.f);
        o.y = fmaxf((acc.y * dd + bi.y - mm.y) * (gg.y * rsqrtf(vv.y + EPSV)) + bbv.y, 0.f);
        o.z = fmaxf((acc.z * dd + bi.z - mm.z) * (gg.z * rsqrtf(vv.z + EPSV)) + bbv.z, 0.f);
        o.w = fmaxf((acc.w * dd + bi.w - mm.w) * (gg.w * rsqrtf(vv.w + EPSV)) + bbv.w, 0.f);
        ((float4*)out)[(long)w * 8 + c] = o;
    }
}

// ---------------- fused GAT (warp/node, float4): single-sweep agg ----------------
// MODE 0: F=32 (rows 64f), 2 neighbors/iter; epilogue bias+ReLU.
// MODE 1: F=16 (rows 32f), 4 neighbors/iter; epilogue bias+log_softmax.
template <int MODE>
__global__ void k_gat_agg(const float* __restrict__ hg, float* __restrict__ out,
                          const float* __restrict__ bias, int n) {
    int w = (blockIdx.x * blockDim.x + threadIdx.x) >> 5;
    int lane = threadIdx.x & 31;
    if (w >= n) return;
    const float4* hg4 = (const float4*)hg;
    int r0 = g_rowptr[w], r1 = g_rowptr[w + 1];
    float ald0 = g_al[w * 4 + 2], ald1 = g_al[w * 4 + 3];
    float w0 = expf(lrelu(g_al[w * 4 + 0] + ald0));
    float w1 = expf(lrelu(g_al[w * 4 + 1] + ald1));
    float s0p = (lane == 0) ? w0 : 0.f;
    float s1p = (lane == 0) ? w1 : 0.f;

    if (MODE == 0) {
        int g = lane >> 4;   // neighbor slot 0..1
        int c = lane & 15;   // chunk within 64-float row; c<8 head0, c>=8 head1
        float selfw = (c < 8) ? w0 : w1;
        float4 acc = make_float4(0.f, 0.f, 0.f, 0.f);
        if (g == 0) {
            float4 hv = hg4[(long)w * 16 + c];
            acc.x = hv.x * selfw; acc.y = hv.y * selfw; acc.z = hv.z * selfw; acc.w = hv.w * selfw;
        }
        for (int base = r0; base < r1; base += 32) {
            int j = base + lane;
            int cnt = min(32, r1 - base);
            int sj = 0; float a0 = 0.f, a1 = 0.f;
            if (j < r1) {
                sj = g_csr[j];
                float2 av = *(const float2*)&g_al[sj * 4];
                a0 = expf(lrelu(av.x + ald0));
                a1 = expf(lrelu(av.y + ald1));
            }
            s0p += a0; s1p += a1;
            for (int t = 0; t < cnt; t += 2) {
                int q = t + g;
                int s = __shfl_sync(0xffffffffu, sj, q);
                float b0 = __shfl_sync(0xffffffffu, a0, q);
                float b1 = __shfl_sync(0xffffffffu, a1, q);
                if (q < cnt) {
                    float bwt = (c < 8) ? b0 : b1;
                    float4 v = hg4[(long)s * 16 + c];
                    acc.x = fmaf(v.x, bwt, acc.x);
                    acc.y = fmaf(v.y, bwt, acc.y);
                    acc.z = fmaf(v.z, bwt, acc.z);
                    acc.w = fmaf(v.w, bwt, acc.w);
                }
            }
        }
        f4red(acc, 16);   // combine the two neighbor slots
        float s0 = wsum32(s0p), s1 = wsum32(s1p);
        // head combine: partner lane (xor 8) holds the other head, same features
        float4 part;
        part.x = __shfl_xor_sync(0xffffffffu, acc.x, 8);
        part.y = __shfl_xor_sync(0xffffffffu, acc.y, 8);
        part.z = __shfl_xor_sync(0xffffffffu, acc.z, 8);
        part.w = __shfl_xor_sync(0xffffffffu, acc.w, 8);
        if (g == 0 && c < 8) {
            float i0 = 0.5f / s0, i1 = 0.5f / s1;
            const float4* b4 = (const float4*)bias;
            float4 bi = __ldg(&b4[c]);
            float4 o;
            o.x = fmaxf(acc.x * i0 + part.x * i1 + bi.x, 0.f);
            o.y = fmaxf(acc.y * i0 + part.y * i1 + bi.y, 0.f);
            o.z = fmaxf(acc.z * i0 + part.z * i1 + bi.z, 0.f);
            o.w = fmaxf(acc.w * i0 + part.w * i1 + bi.w, 0.f);
            ((float4*)out)[(long)w * 8 + c] = o;
        }
    } else {
        int g = lane >> 3;  // neighbor slot 0..3
        int c = lane & 7;   // chunk within 32-float row; c<4 head0, c>=4 head1
        float selfw = (c < 4) ? w0 : w1;
        float4 acc = make_float4(0.f, 0.f, 0.f, 0.f);
        if (g == 0) {
            float4 hv = hg4[(long)w * 8 + c];
            acc.x = hv.x * selfw; acc.y = hv.y * selfw; acc.z = hv.z * selfw; acc.w = hv.w * selfw;
        }
        for (int base = r0; base < r1; base += 32) {
            int j = base + lane;
            int cnt = min(32, r1 - base);
            int sj = 0; float a0 = 0.f, a1 = 0.f;
            if (j < r1) {
                sj = g_csr[j];
                float2 av = *(const float2*)&g_al[sj * 4];
                a0 = expf(lrelu(av.x + ald0));
                a1 = expf(lrelu(av.y + ald1));
            }
            s0p += a0; s1p += a1;
            for (int t = 0; t < cnt; t += 4) {
                int q = t + g;
                int s = __shfl_sync(0xffffffffu, sj, q);
                float b0 = __shfl_sync(0xffffffffu, a0, q);
                float b1 = __shfl_sync(0xffffffffu, a1, q);
                if (q < cnt) {
                    float bwt = (c < 4) ? b0 : b1;
                    float4 v = hg4[(long)s * 8 + c];
                    acc.x = fmaf(v.x, bwt, acc.x);
                    acc.y = fmaf(v.y, bwt, acc.y);
                    acc.z = fmaf(v.z, bwt, acc.z);
                    acc.w = fmaf(v.w, bwt, acc.w);
                }
            }
        }
        f4red(acc, 8); f4red(acc, 16);
        float s0 = wsum32(s0p), s1 = wsum32(s1p);
        float inv = 1.f / ((c < 4) ? s0 : s1);
        float4 v4;
        v4.x = acc.x * inv; v4.y = acc.y * inv; v4.z = acc.z * inv; v4.w = acc.w * inv;
        // head mean: partner (xor 4) holds other head, same features
        float4 pr;
        pr.x = __shfl_xor_sync(0xffffffffu, v4.x, 4);
        pr.y = __shfl_xor_sync(0xffffffffu, v4.y, 4);
        pr.z = __shfl_xor_sync(0xffffffffu, v4.z, 4);
        pr.w = __shfl_xor_sync(0xffffffffu, v4.w, 4);
        const float4* b4 = (const float4*)bias;
        float4 bi = __ldg(&b4[c & 3]);
        float4 vm;
        vm.x = 0.5f * (v4.x + pr.x) + bi.x;
        vm.y = 0.5f * (v4.y + pr.y) + bi.y;
        vm.z = 0.5f * (v4.z + pr.z) + bi.z;
        vm.w = 0.5f * (v4.w + pr.w) + bi.w;
        // log_softmax over 16 classes spread across chunks c&3 (replicated elsewhere)
        float mx = fmaxf(fmaxf(vm.x, vm.y), fmaxf(vm.z, vm.w));
        mx = fmaxf(mx, __shfl_xor_sync(0xffffffffu, mx, 1));
        mx = fmaxf(mx, __shfl_xor_sync(0xffffffffu, mx, 2));
        float se = expf(vm.x - mx) + expf(vm.y - mx) + expf(vm.z - mx) + expf(vm.w - mx);
        se += __shfl_xor_sync(0xffffffffu, se, 1);
        se += __shfl_xor_sync(0xffffffffu, se, 2);
        float ls = logf(se) + mx;
        if (lane < 4) {
            float4 o;
            o.x = vm.x - ls; o.y = vm.y - ls; o.z = vm.z - ls; o.w = vm.w - ls;
            ((float4*)out)[(long)w * 4 + c] = o;
        }
    }
}

// ---------------- host ----------------
static inline int cdiv(long a, int b) { return (int)((a + b - 1) / b); }

extern "C" void kernel_launch(void* const* d_in, const int* in_sizes, int n_in,
                              void* d_out, int out_size) {
    const float* x   = (const float*)d_in[0];
    const int*   ei  = (const int*)d_in[1];
    const float* g1W = (const float*)d_in[2];
    const float* g1b = (const float*)d_in[3];
    const float* b1g = (const float*)d_in[4];
    const float* b1b = (const float*)d_in[5];
    const float* b1m = (const float*)d_in[6];
    const float* b1v = (const float*)d_in[7];
    const float* a1W = (const float*)d_in[8];
    const float* a1s = (const float*)d_in[9];
    const float* a1d = (const float*)d_in[10];
    const float* a1b = (const float*)d_in[11];
    const float* g2W = (const float*)d_in[12];
    const float* g2b = (const float*)d_in[13];
    const float* b2g = (const float*)d_in[14];
    const float* b2b = (const float*)d_in[15];
    const float* b2m = (const float*)d_in[16];
    const float* b2v = (const float*)d_in[17];
    const float* a2W = (const float*)d_in[18];
    const float* a2s = (const float*)d_in[19];
    const float* a2d = (const float*)d_in[20];
    const float* a2b = (const float*)d_in[21];

    int n = in_sizes[0] / FIN;
    int e = in_sizes[1] / 2;
    const int* src = ei;
    const int* dst = ei + e;

    float *pA, *pB;
    cudaGetSymbolAddress((void**)&pA, g_bufA);
    cudaGetSymbolAddress((void**)&pB, g_bufB);

    const int B = 256;
    int nwarp_blocks = cdiv((long)n * 32, B);

    // ---- CSR build ----
    k_zero_deg<<<cdiv(n, B), B>>>(n);
    k_hist<<<cdiv(e, B), B>>>(dst, e);
    k_scan<<<1, 1024>>>(n);
    k_scatter<<<cdiv(e, B), B>>>(src, dst, e);

    // ---- GCN1 ----
    k_gemm_t<FIN, FHID, 32, 0><<<cdiv(n, 32), B>>>(x, g1W, pA, nullptr, nullptr, n);
    k_gcn_agg<<<nwarp_blocks, B>>>(pA, pB, g1b, b1g, b1b, b1m, b1v, n);

    // ---- GAT1 ----
    k_gemm_t<FHID, 64, 16, 1><<<cdiv(n, 16), B>>>(pB, a1W, pA, a1s, a1d, n);
    k_gat_agg<0><<<nwarp_blocks, B>>>(pA, pB, a1b, n);

    // ---- GCN2 ----
    k_gemm_t<FHID, FHID, 32, 0><<<cdiv(n, 32), B>>>(pB, g2W, pA, nullptr, nullptr, n);
    k_gcn_agg<<<nwarp_blocks, B>>>(pA, pB, g2b, b2g, b2b, b2m, b2v, n);

    // ---- GAT2 + final log_softmax ----
    k_gemm_t<FHID, 2 * FOUT, 32, 2><<<cdiv(n, 32), B>>>(pB, a2W, pA, a2s, a2d, n);
    k_gat_agg<1><<<nwarp_blocks, B>>>(pA, (float*)d_out, a2b, n);
}

// round 6
// speedup vs baseline: 1.4137x; 1.0375x over previous
#include <cuda_runtime.h>
#include <math.h>

#define NN 100000
#define EMAX 1600000
#define FIN 128
#define FHID 32
#define FOUT 16
#define EPSV 1e-5f
#define NSLOPE 0.2f

// ---------------- scratch ----------------
__device__ float g_bufA[NN * 64];
__device__ float g_bufB[NN * 64];
__device__ float g_dinv[NN];
__device__ int   g_deg[NN];
__device__ int   g_rowptr[NN + 1];
__device__ int   g_cursor[NN];
__device__ int   g_csr[EMAX];
__device__ float g_al[NN * 4];   // [als0, als1, ald0, ald1] per node

// ---------------- helpers ----------------
__device__ __forceinline__ float lrelu(float x) { return x > 0.f ? x : NSLOPE * x; }

// ---------------- CSR build ----------------
__global__ void k_zero_deg(int n) {
    int i = blockIdx.x * blockDim.x + threadIdx.x;
    if (i < n) g_deg[i] = 0;
}
__global__ void k_hist(const int* __restrict__ dst, int e) {
    int i = blockIdx.x * blockDim.x + threadIdx.x;
    if (i < e) atomicAdd(&g_deg[dst[i]], 1);
}
__global__ void k_scan(int n) {
    __shared__ int ssum[1024];
    int t = threadIdx.x;
    int chunk = (n + 1023) / 1024;
    int lo = t * chunk, hi = min(lo + chunk, n);
    int s = 0;
    for (int i = lo; i < hi; ++i) s += g_deg[i];
    ssum[t] = s;
    __syncthreads();
#pragma unroll
    for (int off = 1; off < 1024; off <<= 1) {
        int v = (t >= off) ? ssum[t - off] : 0;
        __syncthreads();
        ssum[t] += v;
        __syncthreads();
    }
    int run = t ? ssum[t - 1] : 0;
    for (int i = lo; i < hi; ++i) {
        int d = g_deg[i];
        g_rowptr[i] = run;
        g_cursor[i] = run;
        g_dinv[i] = rsqrtf((float)(d + 1));
        run += d;
    }
    if (t == 1023) g_rowptr[n] = ssum[1023];
}
__global__ void k_scatter(const int* __restrict__ src, const int* __restrict__ dst, int e) {
    int i = blockIdx.x * blockDim.x + threadIdx.x;
    if (i >= e) return;
    int pos = atomicAdd(&g_cursor[dst[i]], 1);
    g_csr[pos] = src[i];
}

// ---------------- tiled GEMM: Y[n,F] = X[n,K] @ W[K,F] ----------------
// Thread owns 4 consecutive cols of one row. Per k: 1 bcast LDS + 1 LDS.128 + 4 FMA.
// DSCALE: multiply output row by g_dinv[row] (pre-scaling for GCN gather).
// ALMODE 1 (F=64): per-head logits, reduce over 8 lanes (xor 1,2,4).
// ALMODE 2 (F=32): per-head logits, reduce over 4 lanes (xor 1,2).
template <int K, int F, int RPB, int ALMODE, int DSCALE>
__global__ void k_gemm_t(const float* __restrict__ X, const float* __restrict__ W,
                         float* __restrict__ Y,
                         const float* __restrict__ a_s, const float* __restrict__ a_d,
                         int n) {
    constexpr int CG = F / 4;
    constexpr int KP = K + 1;
    __shared__ float Ws[K * F];
    __shared__ float Xs[RPB * KP];
    int tid = threadIdx.x;
    for (int i = tid; i < K * F; i += 256) Ws[i] = W[i];
    int row0 = blockIdx.x * RPB;
    for (int i = tid; i < RPB * K; i += 256) {
        int r = i / K, kk = i % K;
        int gr = row0 + r;
        Xs[r * KP + kk] = (gr < n) ? X[(long)gr * K + kk] : 0.f;
    }
    __syncthreads();
    int cg = tid % CG, row = tid / CG;
    int col0 = cg * 4;
    float4 acc = make_float4(0.f, 0.f, 0.f, 0.f);
#pragma unroll
    for (int k = 0; k < K; ++k) {
        float xv = Xs[row * KP + k];
        float4 wv = *(const float4*)&Ws[k * F + col0];
        acc.x = fmaf(xv, wv.x, acc.x);
        acc.y = fmaf(xv, wv.y, acc.y);
        acc.z = fmaf(xv, wv.z, acc.z);
        acc.w = fmaf(xv, wv.w, acc.w);
    }
    int gr = row0 + row;
    if (gr < n) {
        float4 o = acc;
        if (DSCALE) {
            float dv = g_dinv[gr];
            o.x *= dv; o.y *= dv; o.z *= dv; o.w *= dv;
        }
        ((float4*)Y)[(long)gr * CG + cg] = o;
    }
    if (ALMODE) {
        float4 as4 = *(const float4*)&a_s[col0];
        float4 ad4 = *(const float4*)&a_d[col0];
        float s = acc.x * as4.x + acc.y * as4.y + acc.z * as4.z + acc.w * as4.w;
        float d = acc.x * ad4.x + acc.y * ad4.y + acc.z * ad4.z + acc.w * ad4.w;
        if (ALMODE == 1) {  // reduce across 8 col-groups of a head
            s += __shfl_xor_sync(0xffffffffu, s, 1);
            d += __shfl_xor_sync(0xffffffffu, d, 1);
            s += __shfl_xor_sync(0xffffffffu, s, 2);
            d += __shfl_xor_sync(0xffffffffu, d, 2);
            s += __shfl_xor_sync(0xffffffffu, s, 4);
            d += __shfl_xor_sync(0xffffffffu, d, 4);
            int head = col0 >> 5;
            if ((cg & 7) == 0 && gr < n) {
                g_al[gr * 4 + head] = s;
                g_al[gr * 4 + 2 + head] = d;
            }
        } else {            // ALMODE 2: 4 col-groups per head
            s += __shfl_xor_sync(0xffffffffu, s, 1);
            d += __shfl_xor_sync(0xffffffffu, d, 1);
            s += __shfl_xor_sync(0xffffffffu, s, 2);
            d += __shfl_xor_sync(0xffffffffu, d, 2);
            int head = col0 >> 4;
            if ((cg & 3) == 0 && gr < n) {
                g_al[gr * 4 + head] = s;
                g_al[gr * 4 + 2 + head] = d;
            }
        }
    }
}

// ---------------- GCN gather: 8 lanes/node, shuffle-free ----------------
// h pre-scaled by dinv[src]; out = relu(bn(dd*(self + sum_nb) + bias))
__global__ void k_gcn_agg(const float* __restrict__ h, float* __restrict__ out,
                          const float* __restrict__ bias,
                          const float* __restrict__ bg, const float* __restrict__ bb,
                          const float* __restrict__ bm, const float* __restrict__ bv, int n) {
    int t = blockIdx.x * blockDim.x + threadIdx.x;
    int w = t >> 3, c = t & 7;
    if (w >= n) return;
    const float4* h4 = (const float4*)h;
    int r0 = g_rowptr[w], r1 = g_rowptr[w + 1];
    float dd = g_dinv[w];
    float4 acc = __ldg(&h4[(long)w * 8 + c]);   // self (pre-scaled)
#pragma unroll 4
    for (int j = r0; j < r1; ++j) {
        int s = __ldg(&g_csr[j]);
        float4 v = __ldg(&h4[(long)s * 8 + c]);
        acc.x += v.x; acc.y += v.y; acc.z += v.z; acc.w += v.w;
    }
    const float4* b4 = (const float4*)bias;
    const float4* g4 = (const float4*)bg;
    const float4* bb4 = (const float4*)bb;
    const float4* m4 = (const float4*)bm;
    const float4* v4 = (const float4*)bv;
    float4 bi = __ldg(&b4[c]), gg = __ldg(&g4[c]), bbv = __ldg(&bb4[c]);
    float4 mm = __ldg(&m4[c]), vv = __ldg(&v4[c]);
    float4 o;
    o.x = fmaxf((acc.x * dd + bi.x - mm.x) * (gg.x * rsqrtf(vv.x + EPSV)) + bbv.x, 0.f);
    o.y = fmaxf((acc.y * dd + bi.y - mm.y) * (gg.y * rsqrtf(vv.y + EPSV)) + bbv.y, 0.f);
    o.z = fmaxf((acc.z * dd + bi.z - mm.z) * (gg.z * rsqrtf(vv.z + EPSV)) + bbv.z, 0.f);
    o.w = fmaxf((acc.w * dd + bi.w - mm.w) * (gg.w * rsqrtf(vv.w + EPSV)) + bbv.w, 0.f);
    ((float4*)out)[(long)w * 8 + c] = o;
}

// ---------------- GAT1 gather: 8 lanes/node, lane owns head0+head1 chunks ----------------
__global__ void k_gat1_agg(const float* __restrict__ hg, float* __restrict__ out,
                           const float* __restrict__ bias, int n) {
    int t = blockIdx.x * blockDim.x + threadIdx.x;
    int w = t >> 3, c = t & 7;
    if (w >= n) return;
    const float4* hg4 = (const float4*)hg;
    int r0 = g_rowptr[w], r1 = g_rowptr[w + 1];
    float ald0 = g_al[w * 4 + 2], ald1 = g_al[w * 4 + 3];
    float w0 = __expf(lrelu(g_al[w * 4 + 0] + ald0));
    float w1 = __expf(lrelu(g_al[w * 4 + 1] + ald1));
    float s0 = w0, s1 = w1;
    float4 h0 = __ldg(&hg4[(long)w * 16 + c]);
    float4 h1 = __ldg(&hg4[(long)w * 16 + 8 + c]);
    float4 acc0, acc1;
    acc0.x = h0.x * w0; acc0.y = h0.y * w0; acc0.z = h0.z * w0; acc0.w = h0.w * w0;
    acc1.x = h1.x * w1; acc1.y = h1.y * w1; acc1.z = h1.z * w1; acc1.w = h1.w * w1;
#pragma unroll 2
    for (int j = r0; j < r1; ++j) {
        int s = __ldg(&g_csr[j]);
        float2 av = *(const float2*)&g_al[s * 4];
        float a0 = __expf(lrelu(av.x + ald0));
        float a1 = __expf(lrelu(av.y + ald1));
        s0 += a0; s1 += a1;
        float4 v0 = __ldg(&hg4[(long)s * 16 + c]);
        float4 v1 = __ldg(&hg4[(long)s * 16 + 8 + c]);
        acc0.x = fmaf(v0.x, a0, acc0.x); acc0.y = fmaf(v0.y, a0, acc0.y);
        acc0.z = fmaf(v0.z, a0, acc0.z); acc0.w = fmaf(v0.w, a0, acc0.w);
        acc1.x = fmaf(v1.x, a1, acc1.x); acc1.y = fmaf(v1.y, a1, acc1.y);
        acc1.z = fmaf(v1.z, a1, acc1.z); acc1.w = fmaf(v1.w, a1, acc1.w);
    }
    float i0 = 0.5f / s0, i1 = 0.5f / s1;
    const float4* b4 = (const float4*)bias;
    float4 bi = __ldg(&b4[c]);
    float4 o;
    o.x = fmaxf(acc0.x * i0 + acc1.x * i1 + bi.x, 0.f);
    o.y = fmaxf(acc0.y * i0 + acc1.y * i1 + bi.y, 0.f);
    o.z = fmaxf(acc0.z * i0 + acc1.z * i1 + bi.z, 0.f);
    o.w = fmaxf(acc0.w * i0 + acc1.w * i1 + bi.w, 0.f);
    ((float4*)out)[(long)w * 8 + c] = o;
}

// ---------------- GAT2 gather: 4 lanes/node, both heads in-lane + log_softmax ----------------
__global__ void k_gat2_agg(const float* __restrict__ hg, float* __restrict__ out,
                           const float* __restrict__ bias, int n) {
    int t = blockIdx.x * blockDim.x + threadIdx.x;
    int w = t >> 2, c = t & 3;
    if (w >= n) return;
    const float4* hg4 = (const float4*)hg;
    int r0 = g_rowptr[w], r1 = g_rowptr[w + 1];
    float ald0 = g_al[w * 4 + 2], ald1 = g_al[w * 4 + 3];
    float w0 = __expf(lrelu(g_al[w * 4 + 0] + ald0));
    float w1 = __expf(lrelu(g_al[w * 4 + 1] + ald1));
    float s0 = w0, s1 = w1;
    float4 h0 = __ldg(&hg4[(long)w * 8 + c]);
    float4 h1 = __ldg(&hg4[(long)w * 8 + 4 + c]);
    float4 acc0, acc1;
    acc0.x = h0.x * w0; acc0.y = h0.y * w0; acc0.z = h0.z * w0; acc0.w = h0.w * w0;
    acc1.x = h1.x * w1; acc1.y = h1.y * w1; acc1.z = h1.z * w1; acc1.w = h1.w * w1;
#pragma unroll 2
    for (int j = r0; j < r1; ++j) {
        int s = __ldg(&g_csr[j]);
        float2 av = *(const float2*)&g_al[s * 4];
        float a0 = __expf(lrelu(av.x + ald0));
        float a1 = __expf(lrelu(av.y + ald1));
        s0 += a0; s1 += a1;
        float4 v0 = __ldg(&hg4[(long)s * 8 + c]);
        float4 v1 = __ldg(&hg4[(long)s * 8 + 4 + c]);
        acc0.x = fmaf(v0.x, a0, acc0.x); acc0.y = fmaf(v0.y, a0, acc0.y);
        acc0.z = fmaf(v0.z, a0, acc0.z); acc0.w = fmaf(v0.w, a0, acc0.w);
        acc1.x = fmaf(v1.x, a1, acc1.x); acc1.y = fmaf(v1.y, a1, acc1.y);
        acc1.z = fmaf(v1.z, a1, acc1.z); acc1.w = fmaf(v1.w, a1, acc1.w);
    }
    float i0 = 0.5f / s0, i1 = 0.5f / s1;
    const float4* b4 = (const float4*)bias;
    float4 bi = __ldg(&b4[c]);
    float4 vm;
    vm.x = acc0.x * i0 + acc1.x * i1 + bi.x;
    vm.y = acc0.y * i0 + acc1.y * i1 + bi.y;
    vm.z = acc0.z * i0 + acc1.z * i1 + bi.z;
    vm.w = acc0.w * i0 + acc1.w * i1 + bi.w;
    // log_softmax over 16 classes = 4 lanes x 4 values (lane groups are 4-aligned)
    float mx = fmaxf(fmaxf(vm.x, vm.y), fmaxf(vm.z, vm.w));
    mx = fmaxf(mx, __shfl_xor_sync(0xffffffffu, mx, 1));
    mx = fmaxf(mx, __shfl_xor_sync(0xffffffffu, mx, 2));
    float se = __expf(vm.x - mx) + __expf(vm.y - mx) + __expf(vm.z - mx) + __expf(vm.w - mx);
    se += __shfl_xor_sync(0xffffffffu, se, 1);
    se += __shfl_xor_sync(0xffffffffu, se, 2);
    float ls = __logf(se) + mx;
    float4 o;
    o.x = vm.x - ls; o.y = vm.y - ls; o.z = vm.z - ls; o.w = vm.w - ls;
    ((float4*)out)[(long)w * 4 + c] = o;
}

// ---------------- host ----------------
static inline int cdiv(long a, int b) { return (int)((a + b - 1) / b); }

extern "C" void kernel_launch(void* const* d_in, const int* in_sizes, int n_in,
                              void* d_out, int out_size) {
    const float* x   = (const float*)d_in[0];
    const int*   ei  = (const int*)d_in[1];
    const float* g1W = (const float*)d_in[2];
    const float* g1b = (const float*)d_in[3];
    const float* b1g = (const float*)d_in[4];
    const float* b1b = (const float*)d_in[5];
    const float* b1m = (const float*)d_in[6];
    const float* b1v = (const float*)d_in[7];
    const float* a1W = (const float*)d_in[8];
    const float* a1s = (const float*)d_in[9];
    const float* a1d = (const float*)d_in[10];
    const float* a1b = (const float*)d_in[11];
    const float* g2W = (const float*)d_in[12];
    const float* g2b = (const float*)d_in[13];
    const float* b2g = (const float*)d_in[14];
    const float* b2b = (const float*)d_in[15];
    const float* b2m = (const float*)d_in[16];
    const float* b2v = (const float*)d_in[17];
    const float* a2W = (const float*)d_in[18];
    const float* a2s = (const float*)d_in[19];
    const float* a2d = (const float*)d_in[20];
    const float* a2b = (const float*)d_in[21];

    int n = in_sizes[0] / FIN;
    int e = in_sizes[1] / 2;
    const int* src = ei;
    const int* dst = ei + e;

    float *pA, *pB;
    cudaGetSymbolAddress((void**)&pA, g_bufA);
    cudaGetSymbolAddress((void**)&pB, g_bufB);

    const int B = 256;

    // ---- CSR build ----
    k_zero_deg<<<cdiv(n, B), B>>>(n);
    k_hist<<<cdiv(e, B), B>>>(dst, e);
    k_scan<<<1, 1024>>>(n);
    k_scatter<<<cdiv(e, B), B>>>(src, dst, e);

    // ---- GCN1 (output pre-scaled by dinv) ----
    k_gemm_t<FIN, FHID, 32, 0, 1><<<cdiv(n, 32), B>>>(x, g1W, pA, nullptr, nullptr, n);
    k_gcn_agg<<<cdiv((long)n * 8, B), B>>>(pA, pB, g1b, b1g, b1b, b1m, b1v, n);

    // ---- GAT1 ----
    k_gemm_t<FHID, 64, 16, 1, 0><<<cdiv(n, 16), B>>>(pB, a1W, pA, a1s, a1d, n);
    k_gat1_agg<<<cdiv((long)n * 8, B), B>>>(pA, pB, a1b, n);

    // ---- GCN2 (output pre-scaled by dinv) ----
    k_gemm_t<FHID, FHID, 32, 0, 1><<<cdiv(n, 32), B>>>(pB, g2W, pA, nullptr, nullptr, n);
    k_gcn_agg<<<cdiv((long)n * 8, B), B>>>(pA, pB, g2b, b2g, b2b, b2m, b2v, n);

    // ---- GAT2 + final log_softmax ----
    k_gemm_t<FHID, FHID, 32, 2, 0><<<cdiv(n, 32), B>>>(pB, a2W, pA, a2s, a2d, n);
    k_gat2_agg<<<cdiv((long)n * 4, B), B>>>(pA, (float*)d_out, a2b, n);
}

// round 8
// speedup vs baseline: 2.3497x; 1.6621x over previous
#include <cuda_runtime.h>
#include <math.h>

#define NN 100000
#define EMAX 1600000
#define FIN 128
#define FHID 32
#define FOUT 16
#define EPSV 1e-5f
#define NSLOPE 0.2f

// ---------------- scratch ----------------
__device__ float g_bufA[NN * 64];
__device__ float g_bufB[NN * 64];
__device__ float g_dinv[NN];
__device__ int   g_deg[NN];
__device__ int   g_rowptr[NN + 1];
__device__ int   g_cursor[NN];
__device__ int   g_csr[EMAX];
__device__ float g_al[NN * 4];   // [als0, als1, ald0, ald1] per node
__device__ int   g_bsum[128];
__device__ int   g_boff[128];

// ---------------- helpers ----------------
__device__ __forceinline__ float lrelu(float x) { return x > 0.f ? x : NSLOPE * x; }

// ---------------- CSR build ----------------
__global__ void k_zero_deg(int n) {
    int i = blockIdx.x * blockDim.x + threadIdx.x;
    if (i < n) g_deg[i] = 0;
}
__global__ void k_hist(const int* __restrict__ dst, int e) {
    int i = blockIdx.x * blockDim.x + threadIdx.x;
    if (i < e) atomicAdd(&g_deg[dst[i]], 1);
}
// scan stage A: per-block inclusive scan of 1024 degrees; local-exclusive to rowptr.
__global__ void k_scan_a(int n) {
    __shared__ int sh[1024];
    int t = threadIdx.x;
    int i = blockIdx.x * 1024 + t;
    int d = (i < n) ? g_deg[i] : 0;
    sh[t] = d;
    __syncthreads();
#pragma unroll
    for (int off = 1; off < 1024; off <<= 1) {
        int v = (t >= off) ? sh[t - off] : 0;
        __syncthreads();
        sh[t] += v;
        __syncthreads();
    }
    if (i < n) g_rowptr[i] = sh[t] - d;
    if (t == 1023) g_bsum[blockIdx.x] = sh[1023];
}
// scan stage B: 1 block scans the (<=128) block sums.
__global__ void k_scan_b(int nb, int n) {
    __shared__ int sh[128];
    int t = threadIdx.x;
    int v = (t < nb) ? g_bsum[t] : 0;
    sh[t] = v;
    __syncthreads();
#pragma unroll
    for (int off = 1; off < 128; off <<= 1) {
        int u = (t >= off) ? sh[t - off] : 0;
        __syncthreads();
        sh[t] += u;
        __syncthreads();
    }
    if (t < nb) g_boff[t] = sh[t] - v;
    if (t == 127) g_rowptr[n] = sh[127];
}
// scan stage C: add block offsets; init cursor + dinv.
__global__ void k_scan_c(int n) {
    int i = blockIdx.x * blockDim.x + threadIdx.x;
    if (i >= n) return;
    int r = g_rowptr[i] + g_boff[i >> 10];
    g_rowptr[i] = r;
    g_cursor[i] = r;
    g_dinv[i] = rsqrtf((float)(g_deg[i] + 1));
}
__global__ void k_scatter(const int* __restrict__ src, const int* __restrict__ dst, int e) {
    int i = blockIdx.x * blockDim.x + threadIdx.x;
    if (i >= e) return;
    int pos = atomicAdd(&g_cursor[dst[i]], 1);
    g_csr[pos] = src[i];
}

// ---------------- tiled GEMM: Y[n,F] = X[n,K] @ W[K,F] ----------------
// NT threads/block; thread owns 8 consecutive cols of one row.
// Per k: 1 bcast LDS + 2 LDS.128 + 8 FMA.
// DSCALE: scale output row by g_dinv[row].
// ALMODE 1 (F=64): per-head logits (4 cgs/head), reduce xor 1,2.
// ALMODE 2 (F=32): per-head logits (2 cgs/head), reduce xor 1.
template <int K, int F, int ALMODE, int DSCALE, int NT>
__global__ void k_gemm8(const float* __restrict__ X, const float* __restrict__ W,
                        float* __restrict__ Y,
                        const float* __restrict__ a_s, const float* __restrict__ a_d,
                        int n) {
    constexpr int CG = F / 8;
    constexpr int RPB = NT / CG;
    constexpr int KP = K + 1;
    __shared__ float Ws[K * F];
    __shared__ float Xs[RPB * KP];
    int tid = threadIdx.x;
    for (int i = tid; i < K * F; i += NT) Ws[i] = W[i];
    int row0 = blockIdx.x * RPB;
    for (int i = tid; i < RPB * K; i += NT) {
        int r = i / K, kk = i % K;
        int gr = row0 + r;
        Xs[r * KP + kk] = (gr < n) ? X[(long)gr * K + kk] : 0.f;
    }
    __syncthreads();
    int cg = tid % CG, row = tid / CG;
    int col0 = cg * 8;
    float4 accA = make_float4(0.f, 0.f, 0.f, 0.f);
    float4 accB = make_float4(0.f, 0.f, 0.f, 0.f);
#pragma unroll 16
    for (int k = 0; k < K; ++k) {
        float xv = Xs[row * KP + k];
        float4 wA = *(const float4*)&Ws[k * F + col0];
        float4 wB = *(const float4*)&Ws[k * F + col0 + 4];
        accA.x = fmaf(xv, wA.x, accA.x);
        accA.y = fmaf(xv, wA.y, accA.y);
        accA.z = fmaf(xv, wA.z, accA.z);
        accA.w = fmaf(xv, wA.w, accA.w);
        accB.x = fmaf(xv, wB.x, accB.x);
        accB.y = fmaf(xv, wB.y, accB.y);
        accB.z = fmaf(xv, wB.z, accB.z);
        accB.w = fmaf(xv, wB.w, accB.w);
    }
    int gr = row0 + row;
    if (gr < n) {
        float4 oA = accA, oB = accB;
        if (DSCALE) {
            float dv = g_dinv[gr];
            oA.x *= dv; oA.y *= dv; oA.z *= dv; oA.w *= dv;
            oB.x *= dv; oB.y *= dv; oB.z *= dv; oB.w *= dv;
        }
        ((float4*)Y)[(long)gr * (F / 4) + cg * 2] = oA;
        ((float4*)Y)[(long)gr * (F / 4) + cg * 2 + 1] = oB;
    }
    if (ALMODE) {
        float4 sA = *(const float4*)&a_s[col0];
        float4 sB = *(const float4*)&a_s[col0 + 4];
        float4 dA = *(const float4*)&a_d[col0];
        float4 dB = *(const float4*)&a_d[col0 + 4];
        float s = accA.x * sA.x + accA.y * sA.y + accA.z * sA.z + accA.w * sA.w
                + accB.x * sB.x + accB.y * sB.y + accB.z * sB.z + accB.w * sB.w;
        float d = accA.x * dA.x + accA.y * dA.y + accA.z * dA.z + accA.w * dA.w
                + accB.x * dB.x + accB.y * dB.y + accB.z * dB.z + accB.w * dB.w;
        if (ALMODE == 1) {   // 4 cgs per head
            s += __shfl_xor_sync(0xffffffffu, s, 1);
            d += __shfl_xor_sync(0xffffffffu, d, 1);
            s += __shfl_xor_sync(0xffffffffu, s, 2);
            d += __shfl_xor_sync(0xffffffffu, d, 2);
            int head = cg >> 2;
            if ((cg & 3) == 0 && gr < n) {
                g_al[gr * 4 + head] = s;
                g_al[gr * 4 + 2 + head] = d;
            }
        } else {             // ALMODE 2: 2 cgs per head
            s += __shfl_xor_sync(0xffffffffu, s, 1);
            d += __shfl_xor_sync(0xffffffffu, d, 1);
            int head = cg >> 1;
            if ((cg & 1) == 0 && gr < n) {
                g_al[gr * 4 + head] = s;
                g_al[gr * 4 + 2 + head] = d;
            }
        }
    }
}

// ---------------- GCN gather: 8 lanes/node, shuffle-free ----------------
__global__ void k_gcn_agg(const float* __restrict__ h, float* __restrict__ out,
                          const float* __restrict__ bias,
                          const float* __restrict__ bg, const float* __restrict__ bb,
                          const float* __restrict__ bm, const float* __restrict__ bv, int n) {
    int t = blockIdx.x * blockDim.x + threadIdx.x;
    int w = t >> 3, c = t & 7;
    if (w >= n) return;
    const float4* h4 = (const float4*)h;
    int r0 = g_rowptr[w], r1 = g_rowptr[w + 1];
    float dd = g_dinv[w];
    float4 acc = __ldg(&h4[(long)w * 8 + c]);   // self (pre-scaled)
#pragma unroll 8
    for (int j = r0; j < r1; ++j) {
        int s = __ldg(&g_csr[j]);
        float4 v = __ldg(&h4[(long)s * 8 + c]);
        acc.x += v.x; acc.y += v.y; acc.z += v.z; acc.w += v.w;
    }
    const float4* b4 = (const float4*)bias;
    const float4* g4 = (const float4*)bg;
    const float4* bb4 = (const float4*)bb;
    const float4* m4 = (const float4*)bm;
    const float4* v4 = (const float4*)bv;
    float4 bi = __ldg(&b4[c]), gg = __ldg(&g4[c]), bbv = __ldg(&bb4[c]);
    float4 mm = __ldg(&m4[c]), vv = __ldg(&v4[c]);
    float4 o;
    o.x = fmaxf((acc.x * dd + bi.x - mm.x) * (gg.x * rsqrtf(vv.x + EPSV)) + bbv.x, 0.f);
    o.y = fmaxf((acc.y * dd + bi.y - mm.y) * (gg.y * rsqrtf(vv.y + EPSV)) + bbv.y, 0.f);
    o.z = fmaxf((acc.z * dd + bi.z - mm.z) * (gg.z * rsqrtf(vv.z + EPSV)) + bbv.z, 0.f);
    o.w = fmaxf((acc.w * dd + bi.w - mm.w) * (gg.w * rsqrtf(vv.w + EPSV)) + bbv.w, 0.f);
    ((float4*)out)[(long)w * 8 + c] = o;
}

// ---------------- GAT1 gather: 8 lanes/node ----------------
__global__ void k_gat1_agg(const float* __restrict__ hg, float* __restrict__ out,
                           const float* __restrict__ bias, int n) {
    int t = blockIdx.x * blockDim.x + threadIdx.x;
    int w = t >> 3, c = t & 7;
    if (w >= n) return;
    const float4* hg4 = (const float4*)hg;
    int r0 = g_rowptr[w], r1 = g_rowptr[w + 1];
    float ald0 = g_al[w * 4 + 2], ald1 = g_al[w * 4 + 3];
    float w0 = __expf(lrelu(g_al[w * 4 + 0] + ald0));
    float w1 = __expf(lrelu(g_al[w * 4 + 1] + ald1));
    float s0 = w0, s1 = w1;
    float4 h0 = __ldg(&hg4[(long)w * 16 + c]);
    float4 h1 = __ldg(&hg4[(long)w * 16 + 8 + c]);
    float4 acc0, acc1;
    acc0.x = h0.x * w0; acc0.y = h0.y * w0; acc0.z = h0.z * w0; acc0.w = h0.w * w0;
    acc1.x = h1.x * w1; acc1.y = h1.y * w1; acc1.z = h1.z * w1; acc1.w = h1.w * w1;
#pragma unroll 4
    for (int j = r0; j < r1; ++j) {
        int s = __ldg(&g_csr[j]);
        float2 av = *(const float2*)&g_al[s * 4];
        float a0 = __expf(lrelu(av.x + ald0));
        float a1 = __expf(lrelu(av.y + ald1));
        s0 += a0; s1 += a1;
        float4 v0 = __ldg(&hg4[(long)s * 16 + c]);
        float4 v1 = __ldg(&hg4[(long)s * 16 + 8 + c]);
        acc0.x = fmaf(v0.x, a0, acc0.x); acc0.y = fmaf(v0.y, a0, acc0.y);
        acc0.z = fmaf(v0.z, a0, acc0.z); acc0.w = fmaf(v0.w, a0, acc0.w);
        acc1.x = fmaf(v1.x, a1, acc1.x); acc1.y = fmaf(v1.y, a1, acc1.y);
        acc1.z = fmaf(v1.z, a1, acc1.z); acc1.w = fmaf(v1.w, a1, acc1.w);
    }
    float i0 = 0.5f / s0, i1 = 0.5f / s1;
    const float4* b4 = (const float4*)bias;
    float4 bi = __ldg(&b4[c]);
    float4 o;
    o.x = fmaxf(acc0.x * i0 + acc1.x * i1 + bi.x, 0.f);
    o.y = fmaxf(acc0.y * i0 + acc1.y * i1 + bi.y, 0.f);
    o.z = fmaxf(acc0.z * i0 + acc1.z * i1 + bi.z, 0.f);
    o.w = fmaxf(acc0.w * i0 + acc1.w * i1 + bi.w, 0.f);
    ((float4*)out)[(long)w * 8 + c] = o;
}

// ---------------- GAT2 gather: 4 lanes/node + log_softmax ----------------
__global__ void k_gat2_agg(const float* __restrict__ hg, float* __restrict__ out,
                           const float* __restrict__ bias, int n) {
    int t = blockIdx.x * blockDim.x + threadIdx.x;
    int w = t >> 2, c = t & 3;
    if (w >= n) return;
    const float4* hg4 = (const float4*)hg;
    int r0 = g_rowptr[w], r1 = g_rowptr[w + 1];
    float ald0 = g_al[w * 4 + 2], ald1 = g_al[w * 4 + 3];
    float w0 = __expf(lrelu(g_al[w * 4 + 0] + ald0));
    float w1 = __expf(lrelu(g_al[w * 4 + 1] + ald1));
    float s0 = w0, s1 = w1;
    float4 h0 = __ldg(&hg4[(long)w * 8 + c]);
    float4 h1 = __ldg(&hg4[(long)w * 8 + 4 + c]);
    float4 acc0, acc1;
    acc0.x = h0.x * w0; acc0.y = h0.y * w0; acc0.z = h0.z * w0; acc0.w = h0.w * w0;
    acc1.x = h1.x * w1; acc1.y = h1.y * w1; acc1.z = h1.z * w1; acc1.w = h1.w * w1;
#pragma unroll 4
    for (int j = r0; j < r1; ++j) {
        int s = __ldg(&g_csr[j]);
        float2 av = *(const float2*)&g_al[s * 4];
        float a0 = __expf(lrelu(av.x + ald0));
        float a1 = __expf(lrelu(av.y + ald1));
        s0 += a0; s1 += a1;
        float4 v0 = __ldg(&hg4[(long)s * 8 + c]);
        float4 v1 = __ldg(&hg4[(long)s * 8 + 4 + c]);
        acc0.x = fmaf(v0.x, a0, acc0.x); acc0.y = fmaf(v0.y, a0, acc0.y);
        acc0.z = fmaf(v0.z, a0, acc0.z); acc0.w = fmaf(v0.w, a0, acc0.w);
        acc1.x = fmaf(v1.x, a1, acc1.x); acc1.y = fmaf(v1.y, a1, acc1.y);
        acc1.z = fmaf(v1.z, a1, acc1.z); acc1.w = fmaf(v1.w, a1, acc1.w);
    }
    float i0 = 0.5f / s0, i1 = 0.5f / s1;
    const float4* b4 = (const float4*)bias;
    float4 bi = __ldg(&b4[c]);
    float4 vm;
    vm.x = acc0.x * i0 + acc1.x * i1 + bi.x;
    vm.y = acc0.y * i0 + acc1.y * i1 + bi.y;
    vm.z = acc0.z * i0 + acc1.z * i1 + bi.z;
    vm.w = acc0.w * i0 + acc1.w * i1 + bi.w;
    float mx = fmaxf(fmaxf(vm.x, vm.y), fmaxf(vm.z, vm.w));
    mx = fmaxf(mx, __shfl_xor_sync(0xffffffffu, mx, 1));
    mx = fmaxf(mx, __shfl_xor_sync(0xffffffffu, mx, 2));
    float se = __expf(vm.x - mx) + __expf(vm.y - mx) + __expf(vm.z - mx) + __expf(vm.w - mx);
    se += __shfl_xor_sync(0xffffffffu, se, 1);
    se += __shfl_xor_sync(0xffffffffu, se, 2);
    float ls = __logf(se) + mx;
    float4 o;
    o.x = vm.x - ls; o.y = vm.y - ls; o.z = vm.z - ls; o.w = vm.w - ls;
    ((float4*)out)[(long)w * 4 + c] = o;
}

// ---------------- host ----------------
static inline int cdiv(long a, int b) { return (int)((a + b - 1) / b); }

extern "C" void kernel_launch(void* const* d_in, const int* in_sizes, int n_in,
                              void* d_out, int out_size) {
    const float* x   = (const float*)d_in[0];
    const int*   ei  = (const int*)d_in[1];
    const float* g1W = (const float*)d_in[2];
    const float* g1b = (const float*)d_in[3];
    const float* b1g = (const float*)d_in[4];
    const float* b1b = (const float*)d_in[5];
    const float* b1m = (const float*)d_in[6];
    const float* b1v = (const float*)d_in[7];
    const float* a1W = (const float*)d_in[8];
    const float* a1s = (const float*)d_in[9];
    const float* a1d = (const float*)d_in[10];
    const float* a1b = (const float*)d_in[11];
    const float* g2W = (const float*)d_in[12];
    const float* g2b = (const float*)d_in[13];
    const float* b2g = (const float*)d_in[14];
    const float* b2b = (const float*)d_in[15];
    const float* b2m = (const float*)d_in[16];
    const float* b2v = (const float*)d_in[17];
    const float* a2W = (const float*)d_in[18];
    const float* a2s = (const float*)d_in[19];
    const float* a2d = (const float*)d_in[20];
    const float* a2b = (const float*)d_in[21];

    int n = in_sizes[0] / FIN;
    int e = in_sizes[1] / 2;
    const int* src = ei;
    const int* dst = ei + e;

    float *pA, *pB;
    cudaGetSymbolAddress((void**)&pA, g_bufA);
    cudaGetSymbolAddress((void**)&pB, g_bufB);

    const int B = 256;
    int nb = cdiv(n, 1024);

    // ---- CSR build ----
    k_zero_deg<<<cdiv(n, B), B>>>(n);
    k_hist<<<cdiv(e, B), B>>>(dst, e);
    k_scan_a<<<nb, 1024>>>(n);
    k_scan_b<<<1, 128>>>(nb, n);
    k_scan_c<<<cdiv(n, B), B>>>(n);
    k_scatter<<<cdiv(e, B), B>>>(src, dst, e);

    // ---- GCN1 (output pre-scaled by dinv); 128 thr/block to fit smem ----
    k_gemm8<FIN, FHID, 0, 1, 128><<<cdiv(n, 32), 128>>>(x, g1W, pA, nullptr, nullptr, n);
    k_gcn_agg<<<cdiv((long)n * 8, B), B>>>(pA, pB, g1b, b1g, b1b, b1m, b1v, n);

    // ---- GAT1 ----
    k_gemm8<FHID, 64, 1, 0, 256><<<cdiv(n, 32), 256>>>(pB, a1W, pA, a1s, a1d, n);
    k_gat1_agg<<<cdiv((long)n * 8, B), B>>>(pA, pB, a1b, n);

    // ---- GCN2 (output pre-scaled by dinv) ----
    k_gemm8<FHID, FHID, 0, 1, 256><<<cdiv(n, 64), 256>>>(pB, g2W, pA, nullptr, nullptr, n);
    k_gcn_agg<<<cdiv((long)n * 8, B), B>>>(pA, pB, g2b, b2g, b2b, b2m, b2v, n);

    // ---- GAT2 + final log_softmax ----
    k_gemm8<FHID, FHID, 2, 0, 256><<<cdiv(n, 64), 256>>>(pB, a2W, pA, a2s, a2d, n);
    k_gat2_agg<<<cdiv((long)n * 4, B), B>>>(pA, (float*)d_out, a2b, n);
}

// round 9
// speedup vs baseline: 2.5179x; 1.0716x over previous
#include <cuda_runtime.h>
#include <cuda_fp16.h>
#include <math.h>

#define NN 100000
#define EMAX 1600000
#define FIN 128
#define FHID 32
#define FOUT 16
#define EPSV 1e-5f
#define NSLOPE 0.2f

// ---------------- scratch ----------------
__device__ __half g_hA[NN * 64];
__device__ __half g_hB[NN * 64];
__device__ float g_dinv[NN];
__device__ int   g_deg[NN];
__device__ int   g_rowptr[NN + 1];
__device__ int   g_cursor[NN];
__device__ int   g_csr[EMAX];
__device__ float g_al[NN * 4];   // [als0, als1, ald0, ald1]
__device__ int   g_bsum[128];
__device__ int   g_boff[128];

// ---------------- helpers ----------------
__device__ __forceinline__ float lrelu(float x) { return x > 0.f ? x : NSLOPE * x; }
__device__ __forceinline__ uint4 pack8(const float4& a, const float4& b) {
    union { __half2 h[4]; uint4 u; } pk;
    pk.h[0] = __floats2half2_rn(a.x, a.y);
    pk.h[1] = __floats2half2_rn(a.z, a.w);
    pk.h[2] = __floats2half2_rn(b.x, b.y);
    pk.h[3] = __floats2half2_rn(b.z, b.w);
    return pk.u;
}
__device__ __forceinline__ void unpack8(uint4 u, float4& a, float4& b) {
    union { uint4 u; __half2 h[4]; } pk; pk.u = u;
    float2 t0 = __half22float2(pk.h[0]);
    float2 t1 = __half22float2(pk.h[1]);
    float2 t2 = __half22float2(pk.h[2]);
    float2 t3 = __half22float2(pk.h[3]);
    a.x = t0.x; a.y = t0.y; a.z = t1.x; a.w = t1.y;
    b.x = t2.x; b.y = t2.y; b.z = t3.x; b.w = t3.y;
}

// ---------------- CSR build ----------------
__global__ void k_zero_deg(int n) {
    int i = blockIdx.x * blockDim.x + threadIdx.x;
    if (i < n) g_deg[i] = 0;
}
__global__ void k_hist(const int* __restrict__ dst, int e) {
    int i = blockIdx.x * blockDim.x + threadIdx.x;
    if (i < e) atomicAdd(&g_deg[dst[i]], 1);
}
__global__ void k_scan_a(int n) {
    __shared__ int sh[1024];
    int t = threadIdx.x;
    int i = blockIdx.x * 1024 + t;
    int d = (i < n) ? g_deg[i] : 0;
    sh[t] = d;
    __syncthreads();
#pragma unroll
    for (int off = 1; off < 1024; off <<= 1) {
        int v = (t >= off) ? sh[t - off] : 0;
        __syncthreads();
        sh[t] += v;
        __syncthreads();
    }
    if (i < n) g_rowptr[i] = sh[t] - d;
    if (t == 1023) g_bsum[blockIdx.x] = sh[1023];
}
__global__ void k_scan_b(int nb, int n) {
    __shared__ int sh[128];
    int t = threadIdx.x;
    int v = (t < nb) ? g_bsum[t] : 0;
    sh[t] = v;
    __syncthreads();
#pragma unroll
    for (int off = 1; off < 128; off <<= 1) {
        int u = (t >= off) ? sh[t - off] : 0;
        __syncthreads();
        sh[t] += u;
        __syncthreads();
    }
    if (t < nb) g_boff[t] = sh[t] - v;
    if (t == 127) g_rowptr[n] = sh[127];
}
__global__ void k_scan_c(int n) {
    int i = blockIdx.x * blockDim.x + threadIdx.x;
    if (i >= n) return;
    int r = g_rowptr[i] + g_boff[i >> 10];
    g_rowptr[i] = r;
    g_cursor[i] = r;
    g_dinv[i] = rsqrtf((float)(g_deg[i] + 1));
}
__global__ void k_scatter(const int* __restrict__ src, const int* __restrict__ dst, int e) {
    int i = blockIdx.x * blockDim.x + threadIdx.x;
    if (i >= e) return;
    int pos = atomicAdd(&g_cursor[dst[i]], 1);
    g_csr[pos] = src[i];
}

// ---------------- tiled GEMM: Yh[n,F] = X[n,K] @ W[K,F], output fp16 ----------------
// INHALF: X is __half (else fp32). DSCALE: scale row by g_dinv.
// ALMODE 1 (F=64): logits per head (4 cgs/head), reduce xor 1,2.
// ALMODE 2 (F=32): logits per head (2 cgs/head), reduce xor 1.
template <int K, int F, int ALMODE, int DSCALE, int NT, int INHALF>
__global__ void k_gemm8(const void* __restrict__ Xv, const float* __restrict__ W,
                        __half* __restrict__ Y,
                        const float* __restrict__ a_s, const float* __restrict__ a_d,
                        int n) {
    constexpr int CG = F / 8;
    constexpr int RPB = NT / CG;
    constexpr int KP = K + 1;
    __shared__ float Ws[K * F];
    __shared__ float Xs[RPB * KP];
    int tid = threadIdx.x;
    for (int i = tid; i < K * F; i += NT) Ws[i] = W[i];
    int row0 = blockIdx.x * RPB;
    if (INHALF) {
        const __half* X = (const __half*)Xv;
        for (int i = tid; i < RPB * K; i += NT) {
            int r = i / K, kk = i % K;
            int gr = row0 + r;
            Xs[r * KP + kk] = (gr < n) ? __half2float(X[(long)gr * K + kk]) : 0.f;
        }
    } else {
        const float* X = (const float*)Xv;
        for (int i = tid; i < RPB * K; i += NT) {
            int r = i / K, kk = i % K;
            int gr = row0 + r;
            Xs[r * KP + kk] = (gr < n) ? X[(long)gr * K + kk] : 0.f;
        }
    }
    __syncthreads();
    int cg = tid % CG, row = tid / CG;
    int col0 = cg * 8;
    float4 accA = make_float4(0.f, 0.f, 0.f, 0.f);
    float4 accB = make_float4(0.f, 0.f, 0.f, 0.f);
#pragma unroll 16
    for (int k = 0; k < K; ++k) {
        float xv = Xs[row * KP + k];
        float4 wA = *(const float4*)&Ws[k * F + col0];
        float4 wB = *(const float4*)&Ws[k * F + col0 + 4];
        accA.x = fmaf(xv, wA.x, accA.x);
        accA.y = fmaf(xv, wA.y, accA.y);
        accA.z = fmaf(xv, wA.z, accA.z);
        accA.w = fmaf(xv, wA.w, accA.w);
        accB.x = fmaf(xv, wB.x, accB.x);
        accB.y = fmaf(xv, wB.y, accB.y);
        accB.z = fmaf(xv, wB.z, accB.z);
        accB.w = fmaf(xv, wB.w, accB.w);
    }
    int gr = row0 + row;
    if (gr < n) {
        float4 oA = accA, oB = accB;
        if (DSCALE) {
            float dv = g_dinv[gr];
            oA.x *= dv; oA.y *= dv; oA.z *= dv; oA.w *= dv;
            oB.x *= dv; oB.y *= dv; oB.z *= dv; oB.w *= dv;
        }
        ((uint4*)Y)[(long)gr * CG + cg] = pack8(oA, oB);
    }
    if (ALMODE) {
        float4 sA = *(const float4*)&a_s[col0];
        float4 sB = *(const float4*)&a_s[col0 + 4];
        float4 dA = *(const float4*)&a_d[col0];
        float4 dB = *(const float4*)&a_d[col0 + 4];
        float s = accA.x * sA.x + accA.y * sA.y + accA.z * sA.z + accA.w * sA.w
                + accB.x * sB.x + accB.y * sB.y + accB.z * sB.z + accB.w * sB.w;
        float d = accA.x * dA.x + accA.y * dA.y + accA.z * dA.z + accA.w * dA.w
                + accB.x * dB.x + accB.y * dB.y + accB.z * dB.z + accB.w * dB.w;
        if (ALMODE == 1) {
            s += __shfl_xor_sync(0xffffffffu, s, 1);
            d += __shfl_xor_sync(0xffffffffu, d, 1);
            s += __shfl_xor_sync(0xffffffffu, s, 2);
            d += __shfl_xor_sync(0xffffffffu, d, 2);
            int head = cg >> 2;
            if ((cg & 3) == 0 && gr < n) {
                g_al[gr * 4 + head] = s;
                g_al[gr * 4 + 2 + head] = d;
            }
        } else {
            s += __shfl_xor_sync(0xffffffffu, s, 1);
            d += __shfl_xor_sync(0xffffffffu, d, 1);
            int head = cg >> 1;
            if ((cg & 1) == 0 && gr < n) {
                g_al[gr * 4 + head] = s;
                g_al[gr * 4 + 2 + head] = d;
            }
        }
    }
}

// ---------------- GCN gather: 4 lanes/node (8 halves each) ----------------
__global__ void k_gcn_agg(const __half* __restrict__ h, __half* __restrict__ out,
                          const float* __restrict__ bias,
                          const float* __restrict__ bg, const float* __restrict__ bb,
                          const float* __restrict__ bm, const float* __restrict__ bv, int n) {
    int t = blockIdx.x * blockDim.x + threadIdx.x;
    int w = t >> 2, c = t & 3;
    if (w >= n) return;
    const uint4* h4 = (const uint4*)h;
    int r0 = g_rowptr[w], r1 = g_rowptr[w + 1];
    float dd = g_dinv[w];
    float4 accA, accB;
    unpack8(__ldg(&h4[(long)w * 4 + c]), accA, accB);  // self (pre-scaled)
#pragma unroll 4
    for (int j = r0; j < r1; ++j) {
        int s = __ldg(&g_csr[j]);
        float4 vA, vB;
        unpack8(__ldg(&h4[(long)s * 4 + c]), vA, vB);
        accA.x += vA.x; accA.y += vA.y; accA.z += vA.z; accA.w += vA.w;
        accB.x += vB.x; accB.y += vB.y; accB.z += vB.z; accB.w += vB.w;
    }
    const float4* b4 = (const float4*)bias;
    const float4* g4 = (const float4*)bg;
    const float4* bb4 = (const float4*)bb;
    const float4* m4 = (const float4*)bm;
    const float4* v4 = (const float4*)bv;
    float4 oA, oB;
    {
        float4 bi = __ldg(&b4[c * 2]), gg = __ldg(&g4[c * 2]), bbv = __ldg(&bb4[c * 2]);
        float4 mm = __ldg(&m4[c * 2]), vv = __ldg(&v4[c * 2]);
        oA.x = fmaxf((accA.x * dd + bi.x - mm.x) * (gg.x * rsqrtf(vv.x + EPSV)) + bbv.x, 0.f);
        oA.y = fmaxf((accA.y * dd + bi.y - mm.y) * (gg.y * rsqrtf(vv.y + EPSV)) + bbv.y, 0.f);
        oA.z = fmaxf((accA.z * dd + bi.z - mm.z) * (gg.z * rsqrtf(vv.z + EPSV)) + bbv.z, 0.f);
        oA.w = fmaxf((accA.w * dd + bi.w - mm.w) * (gg.w * rsqrtf(vv.w + EPSV)) + bbv.w, 0.f);
    }
    {
        float4 bi = __ldg(&b4[c * 2 + 1]), gg = __ldg(&g4[c * 2 + 1]), bbv = __ldg(&bb4[c * 2 + 1]);
        float4 mm = __ldg(&m4[c * 2 + 1]), vv = __ldg(&v4[c * 2 + 1]);
        oB.x = fmaxf((accB.x * dd + bi.x - mm.x) * (gg.x * rsqrtf(vv.x + EPSV)) + bbv.x, 0.f);
        oB.y = fmaxf((accB.y * dd + bi.y - mm.y) * (gg.y * rsqrtf(vv.y + EPSV)) + bbv.y, 0.f);
        oB.z = fmaxf((accB.z * dd + bi.z - mm.z) * (gg.z * rsqrtf(vv.z + EPSV)) + bbv.z, 0.f);
        oB.w = fmaxf((accB.w * dd + bi.w - mm.w) * (gg.w * rsqrtf(vv.w + EPSV)) + bbv.w, 0.f);
    }
    ((uint4*)out)[(long)w * 4 + c] = pack8(oA, oB);
}

// ---------------- GAT1 gather: 8 lanes/node (head = c>>2) ----------------
__global__ void k_gat1_agg(const __half* __restrict__ hg, __half* __restrict__ out,
                           const float* __restrict__ bias, int n) {
    int t = blockIdx.x * blockDim.x + threadIdx.x;
    int w = t >> 3, c = t & 7;
    if (w >= n) return;
    const uint4* hg4 = (const uint4*)hg;
    int r0 = g_rowptr[w], r1 = g_rowptr[w + 1];
    float ald0 = g_al[w * 4 + 2], ald1 = g_al[w * 4 + 3];
    float w0 = __expf(lrelu(g_al[w * 4 + 0] + ald0));
    float w1 = __expf(lrelu(g_al[w * 4 + 1] + ald1));
    float s0 = w0, s1 = w1;
    int head = c >> 2;
    float selfw = head ? w1 : w0;
    float4 accA, accB;
    unpack8(__ldg(&hg4[(long)w * 8 + c]), accA, accB);
    accA.x *= selfw; accA.y *= selfw; accA.z *= selfw; accA.w *= selfw;
    accB.x *= selfw; accB.y *= selfw; accB.z *= selfw; accB.w *= selfw;
#pragma unroll 4
    for (int j = r0; j < r1; ++j) {
        int s = __ldg(&g_csr[j]);
        float2 av = *(const float2*)&g_al[s * 4];
        float a0 = __expf(lrelu(av.x + ald0));
        float a1 = __expf(lrelu(av.y + ald1));
        s0 += a0; s1 += a1;
        float aw = head ? a1 : a0;
        float4 vA, vB;
        unpack8(__ldg(&hg4[(long)s * 8 + c]), vA, vB);
        accA.x = fmaf(vA.x, aw, accA.x); accA.y = fmaf(vA.y, aw, accA.y);
        accA.z = fmaf(vA.z, aw, accA.z); accA.w = fmaf(vA.w, aw, accA.w);
        accB.x = fmaf(vB.x, aw, accB.x); accB.y = fmaf(vB.y, aw, accB.y);
        accB.z = fmaf(vB.z, aw, accB.z); accB.w = fmaf(vB.w, aw, accB.w);
    }
    float iown = 0.5f / (head ? s1 : s0);
    float ioth = 0.5f / (head ? s0 : s1);
    // partner lane (xor 4) holds the other head, same relative cols
    float4 pA, pB;
    pA.x = __shfl_xor_sync(0xffffffffu, accA.x, 4);
    pA.y = __shfl_xor_sync(0xffffffffu, accA.y, 4);
    pA.z = __shfl_xor_sync(0xffffffffu, accA.z, 4);
    pA.w = __shfl_xor_sync(0xffffffffu, accA.w, 4);
    pB.x = __shfl_xor_sync(0xffffffffu, accB.x, 4);
    pB.y = __shfl_xor_sync(0xffffffffu, accB.y, 4);
    pB.z = __shfl_xor_sync(0xffffffffu, accB.z, 4);
    pB.w = __shfl_xor_sync(0xffffffffu, accB.w, 4);
    if (head == 0) {
        const float4* b4 = (const float4*)bias;
        float4 biA = __ldg(&b4[c * 2]), biB = __ldg(&b4[c * 2 + 1]);
        float4 oA, oB;
        oA.x = fmaxf(accA.x * iown + pA.x * ioth + biA.x, 0.f);
        oA.y = fmaxf(accA.y * iown + pA.y * ioth + biA.y, 0.f);
        oA.z = fmaxf(accA.z * iown + pA.z * ioth + biA.z, 0.f);
        oA.w = fmaxf(accA.w * iown + pA.w * ioth + biA.w, 0.f);
        oB.x = fmaxf(accB.x * iown + pB.x * ioth + biB.x, 0.f);
        oB.y = fmaxf(accB.y * iown + pB.y * ioth + biB.y, 0.f);
        oB.z = fmaxf(accB.z * iown + pB.z * ioth + biB.z, 0.f);
        oB.w = fmaxf(accB.w * iown + pB.w * ioth + biB.w, 0.f);
        ((uint4*)out)[(long)w * 4 + c] = pack8(oA, oB);
    }
}

// ---------------- GAT2 gather: 4 lanes/node (head = c>>1) + log_softmax ----------------
__global__ void k_gat2_agg(const __half* __restrict__ hg, float* __restrict__ out,
                           const float* __restrict__ bias, int n) {
    int t = blockIdx.x * blockDim.x + threadIdx.x;
    int w = t >> 2, c = t & 3;
    if (w >= n) return;
    const uint4* hg4 = (const uint4*)hg;
    int r0 = g_rowptr[w], r1 = g_rowptr[w + 1];
    float ald0 = g_al[w * 4 + 2], ald1 = g_al[w * 4 + 3];
    float w0 = __expf(lrelu(g_al[w * 4 + 0] + ald0));
    float w1 = __expf(lrelu(g_al[w * 4 + 1] + ald1));
    float s0 = w0, s1 = w1;
    int head = c >> 1;
    float selfw = head ? w1 : w0;
    float4 accA, accB;
    unpack8(__ldg(&hg4[(long)w * 4 + c]), accA, accB);
    accA.x *= selfw; accA.y *= selfw; accA.z *= selfw; accA.w *= selfw;
    accB.x *= selfw; accB.y *= selfw; accB.z *= selfw; accB.w *= selfw;
#pragma unroll 4
    for (int j = r0; j < r1; ++j) {
        int s = __ldg(&g_csr[j]);
        float2 av = *(const float2*)&g_al[s * 4];
        float a0 = __expf(lrelu(av.x + ald0));
        float a1 = __expf(lrelu(av.y + ald1));
        s0 += a0; s1 += a1;
        float aw = head ? a1 : a0;
        float4 vA, vB;
        unpack8(__ldg(&hg4[(long)s * 4 + c]), vA, vB);
        accA.x = fmaf(vA.x, aw, accA.x); accA.y = fmaf(vA.y, aw, accA.y);
        accA.z = fmaf(vA.z, aw, accA.z); accA.w = fmaf(vA.w, aw, accA.w);
        accB.x = fmaf(vB.x, aw, accB.x); accB.y = fmaf(vB.y, aw, accB.y);
        accB.z = fmaf(vB.z, aw, accB.z); accB.w = fmaf(vB.w, aw, accB.w);
    }
    float iown = 0.5f / (head ? s1 : s0);
    float ioth = 0.5f / (head ? s0 : s1);
    float4 pA, pB;
    pA.x = __shfl_xor_sync(0xffffffffu, accA.x, 2);
    pA.y = __shfl_xor_sync(0xffffffffu, accA.y, 2);
    pA.z = __shfl_xor_sync(0xffffffffu, accA.z, 2);
    pA.w = __shfl_xor_sync(0xffffffffu, accA.w, 2);
    pB.x = __shfl_xor_sync(0xffffffffu, accB.x, 2);
    pB.y = __shfl_xor_sync(0xffffffffu, accB.y, 2);
    pB.z = __shfl_xor_sync(0xffffffffu, accB.z, 2);
    pB.w = __shfl_xor_sync(0xffffffffu, accB.w, 2);
    int blk = c & 1;   // class block 0 (cols 0-7) or 1 (cols 8-15)
    const float4* b4 = (const float4*)bias;
    float4 biA = __ldg(&b4[blk * 2]), biB = __ldg(&b4[blk * 2 + 1]);
    float4 vA, vB;
    vA.x = accA.x * iown + pA.x * ioth + biA.x;
    vA.y = accA.y * iown + pA.y * ioth + biA.y;
    vA.z = accA.z * iown + pA.z * ioth + biA.z;
    vA.w = accA.w * iown + pA.w * ioth + biA.w;
    vB.x = accB.x * iown + pB.x * ioth + biB.x;
    vB.y = accB.y * iown + pB.y * ioth + biB.y;
    vB.z = accB.z * iown + pB.z * ioth + biB.z;
    vB.w = accB.w * iown + pB.w * ioth + biB.w;
    // log_softmax over 16 classes = two 8-value blocks on lanes c and c^1
    float mx = fmaxf(fmaxf(vA.x, vA.y), fmaxf(vA.z, vA.w));
    mx = fmaxf(mx, fmaxf(fmaxf(vB.x, vB.y), fmaxf(vB.z, vB.w)));
    mx = fmaxf(mx, __shfl_xor_sync(0xffffffffu, mx, 1));
    float se = __expf(vA.x - mx) + __expf(vA.y - mx) + __expf(vA.z - mx) + __expf(vA.w - mx)
             + __expf(vB.x - mx) + __expf(vB.y - mx) + __expf(vB.z - mx) + __expf(vB.w - mx);
    se += __shfl_xor_sync(0xffffffffu, se, 1);
    float ls = __logf(se) + mx;
    if (head == 0) {
        float4 oA, oB;
        oA.x = vA.x - ls; oA.y = vA.y - ls; oA.z = vA.z - ls; oA.w = vA.w - ls;
        oB.x = vB.x - ls; oB.y = vB.y - ls; oB.z = vB.z - ls; oB.w = vB.w - ls;
        ((float4*)out)[(long)w * 4 + blk * 2] = oA;
        ((float4*)out)[(long)w * 4 + blk * 2 + 1] = oB;
    }
}

// ---------------- host ----------------
static inline int cdiv(long a, int b) { return (int)((a + b - 1) / b); }

extern "C" void kernel_launch(void* const* d_in, const int* in_sizes, int n_in,
                              void* d_out, int out_size) {
    const float* x   = (const float*)d_in[0];
    const int*   ei  = (const int*)d_in[1];
    const float* g1W = (const float*)d_in[2];
    const float* g1b = (const float*)d_in[3];
    const float* b1g = (const float*)d_in[4];
    const float* b1b = (const float*)d_in[5];
    const float* b1m = (const float*)d_in[6];
    const float* b1v = (const float*)d_in[7];
    const float* a1W = (const float*)d_in[8];
    const float* a1s = (const float*)d_in[9];
    const float* a1d = (const float*)d_in[10];
    const float* a1b = (const float*)d_in[11];
    const float* g2W = (const float*)d_in[12];
    const float* g2b = (const float*)d_in[13];
    const float* b2g = (const float*)d_in[14];
    const float* b2b = (const float*)d_in[15];
    const float* b2m = (const float*)d_in[16];
    const float* b2v = (const float*)d_in[17];
    const float* a2W = (const float*)d_in[18];
    const float* a2s = (const float*)d_in[19];
    const float* a2d = (const float*)d_in[20];
    const float* a2b = (const float*)d_in[21];

    int n = in_sizes[0] / FIN;
    int e = in_sizes[1] / 2;
    const int* src = ei;
    const int* dst = ei + e;

    __half *pA, *pB;
    cudaGetSymbolAddress((void**)&pA, g_hA);
    cudaGetSymbolAddress((void**)&pB, g_hB);

    const int B = 256;
    int nb = cdiv(n, 1024);

    // ---- CSR build ----
    k_zero_deg<<<cdiv(n, B), B>>>(n);
    k_hist<<<cdiv(e, B), B>>>(dst, e);
    k_scan_a<<<nb, 1024>>>(n);
    k_scan_b<<<1, 128>>>(nb, n);
    k_scan_c<<<cdiv(n, B), B>>>(n);
    k_scatter<<<cdiv(e, B), B>>>(src, dst, e);

    // ---- GCN1 (pre-scaled by dinv, fp32 input) ----
    k_gemm8<FIN, FHID, 0, 1, 128, 0><<<cdiv(n, 32), 128>>>(x, g1W, pA, nullptr, nullptr, n);
    k_gcn_agg<<<cdiv((long)n * 4, B), B>>>(pA, pB, g1b, b1g, b1b, b1m, b1v, n);

    // ---- GAT1 ----
    k_gemm8<FHID, 64, 1, 0, 256, 1><<<cdiv(n, 32), 256>>>(pB, a1W, pA, a1s, a1d, n);
    k_gat1_agg<<<cdiv((long)n * 8, B), B>>>(pA, pB, a1b, n);

    // ---- GCN2 (pre-scaled by dinv) ----
    k_gemm8<FHID, FHID, 0, 1, 256, 1><<<cdiv(n, 64), 256>>>(pB, g2W, pA, nullptr, nullptr, n);
    k_gcn_agg<<<cdiv((long)n * 4, B), B>>>(pA, pB, g2b, b2g, b2b, b2m, b2v, n);

    // ---- GAT2 + final log_softmax ----
    k_gemm8<FHID, FHID, 2, 0, 256, 1><<<cdiv(n, 64), 256>>>(pB, a2W, pA, a2s, a2d, n);
    k_gat2_agg<<<cdiv((long)n * 4, B), B>>>(pA, (float*)d_out, a2b, n);
}